// round 12
// baseline (speedup 1.0000x reference)
#include <cuda_runtime.h>
#include <cuda_bf16.h>
#include <mma.h>
#include <math.h>
#include <stdint.h>

using namespace nvcuda;

#define B_ 32
#define T_ 128

typedef unsigned long long u64t;

// ---------------- device globals ----------------
__device__ float d_M[4 * 4096];
__device__ float d_out0[B_ * T_ * 4096];
__device__ float d_last[B_ * 4096];
__device__ float d_Gx[(size_t)B_ * T_ * 64 * 128];
__device__ float d_Cx[(size_t)B_ * T_ * 64 * 64];
__device__ __align__(16) unsigned char d_MI[2 * 32768];   // [prec][256x64 bf16]
__device__ __align__(16) unsigned char d_WI[2 * 2 * 122880]; // [layer][prec][320x192 bf16]

// ---------------- helpers ----------------
__device__ __forceinline__ u64t pack_dup(float x) {
    u64t r; asm("mov.b64 %0, {%1,%1};" : "=l"(r) : "f"(x)); return r;
}
__device__ __forceinline__ u64t pack2(float lo, float hi) {
    u64t r; asm("mov.b64 %0, {%1,%2};" : "=l"(r) : "f"(lo), "f"(hi)); return r;
}
__device__ __forceinline__ float2 unpack2(u64t v) {
    float2 f; asm("mov.b64 {%0,%1}, %2;" : "=f"(f.x), "=f"(f.y) : "l"(v)); return f;
}
__device__ __forceinline__ void fma2(u64t& d, u64t a, u64t b) {
    asm("fma.rn.f32x2 %0, %1, %2, %0;" : "+l"(d) : "l"(a), "l"(b));
}
__device__ __forceinline__ uint32_t s_u32(const void* p) {
    return (uint32_t)__cvta_generic_to_shared(p);
}
__device__ __forceinline__ uint32_t mapa_rank(uint32_t a, uint32_t r) {
    uint32_t o;
    asm("mapa.shared::cluster.u32 %0, %1, %2;" : "=r"(o) : "r"(a), "r"(r));
    return o;
}
__device__ __forceinline__ float ldc_f32(uint32_t a) {
    float v;
    asm volatile("ld.shared::cluster.f32 %0, [%1];" : "=f"(v) : "r"(a));
    return v;
}
__device__ __forceinline__ void cp16(void* dst, const void* src) {
    asm volatile("cp.async.cg.shared.global [%0], [%1], 16;"
                 :: "r"(s_u32(dst)), "l"(src));
}
#define CP_COMMIT() asm volatile("cp.async.commit_group;")
#define CP_WAIT0()  asm volatile("cp.async.wait_group 0;")
#define CLUSTER_ARRIVE() asm volatile("barrier.cluster.arrive.aligned;" ::: "memory")
#define CLUSTER_WAIT()   asm volatile("barrier.cluster.wait.aligned;"   ::: "memory")
#define CLUSTER_SYNC() do { CLUSTER_ARRIVE(); CLUSTER_WAIT(); } while (0)

__device__ __forceinline__ float sigmoid_f(float v) {
    return __fdividef(1.f, 1.f + __expf(-v));
}
__device__ __forceinline__ float tanh_f(float v) {
    return 1.f - __fdividef(2.f, __expf(2.f * v) + 1.f);
}

extern __shared__ float smem[];

// ---------------------------------------------------------------------------
__global__ void prep_kernel(const float* __restrict__ S0, const float* __restrict__ S1)
{
    __shared__ float Ss[64 * 64];
    const int s = blockIdx.x;
    const float* S = s ? S1 : S0;
    for (int i = threadIdx.x; i < 4096; i += blockDim.x) Ss[i] = S[i];
    __syncthreads();
    for (int i = threadIdx.x; i < 4096; i += blockDim.x) {
        int m = i >> 6, n = i & 63;
        float acc = 0.f;
        #pragma unroll 8
        for (int p = 0; p < 64; ++p) acc += Ss[m * 64 + p] * Ss[p * 64 + n];
        d_M[(2 * s) * 4096 + i]     = Ss[i];
        d_M[(2 * s + 1) * 4096 + i] = 2.f * acc - (m == n ? 1.f : 0.f);
    }
}

// ---------------------------------------------------------------------------
// Build bf16 hi/lo operand images (plain row-major for wmma).
// MI[np][n], np=k*64+m = M_k[m][n].  WI[kcat][c], kcat=kt*64+kk:
//   c<128 -> Wg[kt*128+kk][c], else Wc[kt*128+kk][c-128].
// ---------------------------------------------------------------------------
__global__ void prep_img(const float* __restrict__ Wg0, const float* __restrict__ Wc0,
                         const float* __restrict__ Wg1, const float* __restrict__ Wc1)
{
    const int gt = blockIdx.x * blockDim.x + threadIdx.x;
    const int gs = gridDim.x * blockDim.x;
    for (int i = gt; i < 16384; i += gs) {
        int np = i >> 6, n = i & 63;
        float v = d_M[(np >> 6) * 4096 + (np & 63) * 64 + n];
        __nv_bfloat16 hi = __float2bfloat16(v);
        __nv_bfloat16 lo = __float2bfloat16(v - __bfloat162float(hi));
        *(__nv_bfloat16*)(d_MI + np * 128 + n * 2) = hi;
        *(__nv_bfloat16*)(d_MI + 32768 + np * 128 + n * 2) = lo;
    }
    for (int i = gt; i < 2 * 61440; i += gs) {
        int l = i / 61440, rem = i % 61440;
        int kcat = rem / 192, c = rem % 192;
        int kt = kcat >> 6, kk = kcat & 63;
        float v;
        if (c < 128) v = (l ? Wg1 : Wg0)[(size_t)(kt * 128 + kk) * 128 + c];
        else         v = (l ? Wc1 : Wc0)[(size_t)(kt * 128 + kk) * 64 + (c - 128)];
        __nv_bfloat16 hi = __float2bfloat16(v);
        __nv_bfloat16 lo = __float2bfloat16(v - __bfloat162float(hi));
        unsigned char* base = d_WI + l * 245760;
        *(__nv_bfloat16*)(base + kcat * 384 + c * 2) = hi;
        *(__nv_bfloat16*)(base + 122880 + kcat * 384 + c * 2) = lo;
    }
}

// ---------------------------------------------------------------------------
// WMMA precompute of Gx/Cx. One (b,t) per CTA, 8 warps.
// smem: A2h [0,40960) 64x320 bf16 | A2l [40960,81920) | SCR [81920,+65536)
// ---------------------------------------------------------------------------
#define PRE2_SMEM (81920 + 65536)

__global__ void __launch_bounds__(256, 1)
pre_wmma(const float* __restrict__ Xin, const float* __restrict__ bg,
         const float* __restrict__ bc, int layer)
{
    unsigned char* sm  = (unsigned char*)smem;
    unsigned char* A2h = sm;
    unsigned char* A2l = sm + 40960;
    unsigned char* SCR = sm + 81920;
    __nv_bfloat16* A2hB = (__nv_bfloat16*)A2h;
    __nv_bfloat16* A2lB = (__nv_bfloat16*)A2l;

    const int tid = threadIdx.x;
    const int w = tid >> 5;
    const int bt = blockIdx.x;

    // x -> A2 tile0 (hi/lo); M images -> SCR
    const float* xsrc = (layer ? d_out0 : Xin) + (size_t)bt * 4096;
    for (int i = tid; i < 4096; i += 256) cp16(SCR + i * 16, d_MI + i * 16);
    CP_COMMIT();
    for (int i = tid; i < 4096; i += 256) {
        int n = i >> 6, f = i & 63;
        float v = xsrc[i];
        __nv_bfloat16 hi = __float2bfloat16(v);
        __nv_bfloat16 lo = __float2bfloat16(v - __bfloat162float(hi));
        A2hB[n * 320 + f] = hi;
        A2lB[n * 320 + f] = lo;
    }
    CP_WAIT0();
    __syncthreads();

    // ---------------- phase 1: xa = M_stack(256x64) @ x(64x64) ----------------
    {
        wmma::fragment<wmma::accumulator, 16, 16, 16, float> acc1[8];
        #pragma unroll
        for (int i = 0; i < 8; ++i) wmma::fill_fragment(acc1[i], 0.f);
        const __nv_bfloat16* Mh = (const __nv_bfloat16*)SCR;
        const __nv_bfloat16* Ml = (const __nv_bfloat16*)(SCR + 32768);
        #pragma unroll
        for (int ks = 0; ks < 4; ++ks) {
            wmma::fragment<wmma::matrix_a, 16, 16, 16, __nv_bfloat16, wmma::row_major> ah[2], al[2];
            wmma::fragment<wmma::matrix_b, 16, 16, 16, __nv_bfloat16, wmma::row_major> bh[4], bl[4];
            #pragma unroll
            for (int mi = 0; mi < 2; ++mi) {
                wmma::load_matrix_sync(ah[mi], Mh + (w * 2 + mi) * 16 * 64 + ks * 16, 64);
                wmma::load_matrix_sync(al[mi], Ml + (w * 2 + mi) * 16 * 64 + ks * 16, 64);
            }
            #pragma unroll
            for (int nt = 0; nt < 4; ++nt) {
                wmma::load_matrix_sync(bh[nt], A2hB + ks * 16 * 320 + nt * 16, 320);
                wmma::load_matrix_sync(bl[nt], A2lB + ks * 16 * 320 + nt * 16, 320);
            }
            #pragma unroll
            for (int mi = 0; mi < 2; ++mi)
                #pragma unroll
                for (int nt = 0; nt < 4; ++nt) {
                    int x = mi * 4 + nt;
                    wmma::mma_sync(acc1[x], ah[mi], bh[nt], acc1[x]);
                    wmma::mma_sync(acc1[x], al[mi], bh[nt], acc1[x]);
                    wmma::mma_sync(acc1[x], ah[mi], bl[nt], acc1[x]);
                }
        }
        __syncthreads();          // all M reads done; SCR reusable
        float* S = (float*)SCR;
        #pragma unroll
        for (int mi = 0; mi < 2; ++mi)
            #pragma unroll
            for (int nt = 0; nt < 4; ++nt)
                wmma::store_matrix_sync(S + (w * 2 + mi) * 16 * 64 + nt * 16,
                                        acc1[mi * 4 + nt], 64, wmma::mem_row_major);
        __syncthreads();
        for (int i = tid; i < 16384; i += 256) {
            int row = i >> 6, f = i & 63;
            int k = row >> 6, m = row & 63;
            float v = S[i];
            __nv_bfloat16 hi = __float2bfloat16(v);
            __nv_bfloat16 lo = __float2bfloat16(v - __bfloat162float(hi));
            A2hB[m * 320 + (k + 1) * 64 + f] = hi;
            A2lB[m * 320 + (k + 1) * 64 + f] = lo;
        }
        __syncthreads();
    }

    // ---------------- phase 2: [x|xa](64x320) @ WI(320x192) ----------------
    {
        wmma::fragment<wmma::accumulator, 16, 16, 16, float> acc2[6];
        #pragma unroll
        for (int i = 0; i < 6; ++i) wmma::fill_fragment(acc2[i], 0.f);
        const int mt = w >> 1, ng = w & 1;
        const unsigned char* gW = d_WI + layer * 245760;

        for (int kt = 0; kt < 5; ++kt) {
            if (kt) __syncthreads();          // prior Wbuf reads done
            for (int i = tid; i < 1536; i += 256) {
                cp16(SCR + i * 16, gW + kt * 24576 + i * 16);
                cp16(SCR + 24576 + i * 16, gW + 122880 + kt * 24576 + i * 16);
            }
            CP_COMMIT(); CP_WAIT0();
            __syncthreads();
            const __nv_bfloat16* WbH = (const __nv_bfloat16*)SCR;
            const __nv_bfloat16* WbL = (const __nv_bfloat16*)(SCR + 24576);
            #pragma unroll
            for (int ks = 0; ks < 4; ++ks) {
                wmma::fragment<wmma::matrix_a, 16, 16, 16, __nv_bfloat16, wmma::row_major> ah, al;
                wmma::load_matrix_sync(ah, A2hB + mt * 16 * 320 + kt * 64 + ks * 16, 320);
                wmma::load_matrix_sync(al, A2lB + mt * 16 * 320 + kt * 64 + ks * 16, 320);
                #pragma unroll
                for (int nt = 0; nt < 6; ++nt) {
                    wmma::fragment<wmma::matrix_b, 16, 16, 16, __nv_bfloat16, wmma::row_major> bh, bl;
                    int nc = (ng * 6 + nt) * 16;
                    wmma::load_matrix_sync(bh, WbH + ks * 16 * 192 + nc, 192);
                    wmma::load_matrix_sync(bl, WbL + ks * 16 * 192 + nc, 192);
                    wmma::mma_sync(acc2[nt], ah, bh, acc2[nt]);
                    wmma::mma_sync(acc2[nt], al, bh, acc2[nt]);
                    wmma::mma_sync(acc2[nt], ah, bl, acc2[nt]);
                }
            }
        }
        __syncthreads();
        float* S = (float*)SCR;
        #pragma unroll
        for (int nt = 0; nt < 6; ++nt)
            wmma::store_matrix_sync(S + mt * 16 * 192 + (ng * 6 + nt) * 16,
                                    acc2[nt], 192, wmma::mem_row_major);
        __syncthreads();
        for (int i = tid; i < 12288; i += 256) {
            int n = i / 192, c = i % 192;
            float v = S[i];
            if (c < 128) d_Gx[(size_t)bt * 8192 + n * 128 + c] = v + bg[c];
            else         d_Cx[(size_t)bt * 4096 + n * 64 + (c - 128)] = v + bc[c - 128];
        }
    }
}

// ---------------------------------------------------------------------------
// Persistent per-layer scan — proven R7/R8 256-thread version (unchanged).
// ---------------------------------------------------------------------------
#define SCAN_SMEM_BYTES (56256 * 4)

__global__ void __launch_bounds__(256, 1) __cluster_dims__(4, 1, 1)
scan_kernel(const float* __restrict__ Wg, const float* __restrict__ Wc,
            const int* __restrict__ lens, int layer)
{
    float* wg_h = smem;
    float* wc_h = smem + 10240;
    float* Ms   = smem + 15360;
    float* h_s  = smem + 32768;
    float* rh_s = smem + 37120;
    float* V_s  = smem + 41472;
    float* rst  = smem + 52992;
    float* ugs  = smem + 54080;
    float* hst  = smem + 55168;

    const int tid = threadIdx.x;
    const int b = blockIdx.x >> 2;
    const int j = blockIdx.x & 3;

    for (int i = tid; i < 10240; i += 256) {
        int k = i >> 11, d = (i >> 5) & 63, c = i & 31;
        int g = (c < 16) ? (j * 16 + c) : (64 + j * 16 + (c - 16));
        wg_h[i] = Wg[(size_t)(k * 128 + 64 + d) * 128 + g];
    }
    for (int i = tid; i < 5120; i += 256) {
        int k = i >> 10, d = (i >> 4) & 63, c = i & 15;
        wc_h[i] = Wc[(size_t)(k * 128 + 64 + d) * 64 + j * 16 + c];
    }
    for (int i = tid; i < 16384; i += 256) {
        int k = i >> 12, r = (i >> 6) & 63, p = i & 63;
        Ms[k * 4352 + r * 68 + p] = d_M[i];
    }
    for (int i = tid; i < 4096; i += 256)
        h_s[(i >> 6) * 68 + (i & 63)] = 0.f;

    int idx_t = lens[b] - 1;
    idx_t = idx_t < 0 ? 0 : (idx_t > T_ - 1 ? T_ - 1 : idx_t);

    uint32_t rbase[4], hbase[4];
    #pragma unroll
    for (int r = 0; r < 4; ++r) {
        rbase[r] = mapa_rank(s_u32(rst), (uint32_t)r);
        hbase[r] = mapa_rank(s_u32(hst), (uint32_t)r);
    }

    const int rg  = tid & 31;
    const int jg  = tid >> 5;
    const int mg  = tid >> 3;
    const int ja4 = (tid & 7) * 4;
    const int ja2 = (tid & 7) * 2;
    const int g0  = (ja4 < 16) ? (j * 16 + ja4) : (64 + j * 16 + (ja4 - 16));
    const int c0  = j * 16 + ja2;

    const float* gxb = d_Gx + (size_t)b * T_ * 8192;
    const float* cxb = d_Cx + (size_t)b * T_ * 4096;

    for (int t = 0; t < T_; ++t) {
        __syncthreads();
        const float* gx = gxb + (size_t)t * 8192;
        const float* cx = cxb + (size_t)t * 4096;
        float4 gA = __ldg((const float4*)(gx + mg * 128 + g0));
        float4 gB = __ldg((const float4*)(gx + (mg + 32) * 128 + g0));
        float2 cA = __ldg((const float2*)(cx + mg * 64 + c0));
        float2 cB = __ldg((const float2*)(cx + (mg + 32) * 64 + c0));

        {   // gate V-phase
            u64t acc[5][4];
            #pragma unroll
            for (int k = 0; k < 5; ++k) { acc[k][0] = acc[k][1] = acc[k][2] = acc[k][3] = 0; }
            const float* h0p = h_s + rg * 68;
            const float* h1p = h_s + (rg + 32) * 68;
            const float* wbase = wg_h + jg * 4;
            #pragma unroll 2
            for (int d4 = 0; d4 < 64; d4 += 4) {
                float4 hv0 = *(const float4*)(h0p + d4);
                float4 hv1 = *(const float4*)(h1p + d4);
                float h0a[4] = {hv0.x, hv0.y, hv0.z, hv0.w};
                float h1a[4] = {hv1.x, hv1.y, hv1.z, hv1.w};
                #pragma unroll
                for (int q = 0; q < 4; ++q) {
                    u64t a0 = pack_dup(h0a[q]);
                    u64t a1 = pack_dup(h1a[q]);
                    #pragma unroll
                    for (int k = 0; k < 5; ++k) {
                        ulonglong2 w = *(const ulonglong2*)(wbase + k * 2048 + (d4 + q) * 32);
                        fma2(acc[k][0], a0, w.x); fma2(acc[k][1], a0, w.y);
                        fma2(acc[k][2], a1, w.x); fma2(acc[k][3], a1, w.y);
                    }
                }
            }
            #pragma unroll
            for (int k = 0; k < 5; ++k) {
                ulonglong2 s;
                s.x = acc[k][0]; s.y = acc[k][1];
                *(ulonglong2*)(V_s + k * 2304 + rg * 36 + jg * 4) = s;
                s.x = acc[k][2]; s.y = acc[k][3];
                *(ulonglong2*)(V_s + k * 2304 + (rg + 32) * 36 + jg * 4) = s;
            }
        }
        __syncthreads();

        {   // gate M-apply + sigmoid
            float4 vA = *(const float4*)(V_s + mg * 36 + ja4);
            float4 vB = *(const float4*)(V_s + (mg + 32) * 36 + ja4);
            u64t y00 = pack2(gA.x + vA.x, gA.y + vA.y);
            u64t y01 = pack2(gA.z + vA.z, gA.w + vA.w);
            u64t y10 = pack2(gB.x + vB.x, gB.y + vB.y);
            u64t y11 = pack2(gB.z + vB.z, gB.w + vB.w);
            for (int k = 1; k < 5; ++k) {
                const float* Mk = Ms + (k - 1) * 4352;
                const float* Vk = V_s + k * 2304;
                #pragma unroll 4
                for (int m = 0; m < 64; m += 4) {
                    float4 mA = *(const float4*)(Mk + mg * 68 + m);
                    float4 mB = *(const float4*)(Mk + (mg + 32) * 68 + m);
                    float mAa[4] = {mA.x, mA.y, mA.z, mA.w};
                    float mBa[4] = {mB.x, mB.y, mB.z, mB.w};
                    #pragma unroll
                    for (int q = 0; q < 4; ++q) {
                        ulonglong2 v = *(const ulonglong2*)(Vk + (m + q) * 36 + ja4);
                        u64t da = pack_dup(mAa[q]);
                        u64t db = pack_dup(mBa[q]);
                        fma2(y00, da, v.x); fma2(y01, da, v.y);
                        fma2(y10, db, v.x); fma2(y11, db, v.y);
                    }
                }
            }
            float2 p00 = unpack2(y00), p01 = unpack2(y01);
            float2 p10 = unpack2(y10), p11 = unpack2(y11);
            float v0a[4] = {p00.x, p00.y, p01.x, p01.y};
            float v1a[4] = {p10.x, p10.y, p11.x, p11.y};
            #pragma unroll
            for (int q = 0; q < 4; ++q) {
                int c = ja4 + q;
                float s0 = sigmoid_f(v0a[q]);
                float s1 = sigmoid_f(v1a[q]);
                if (c < 16) { rst[mg * 17 + c] = s0;        rst[(mg + 32) * 17 + c] = s1; }
                else        { ugs[mg * 17 + c - 16] = s0;   ugs[(mg + 32) * 17 + c - 16] = s1; }
            }
        }

        CLUSTER_ARRIVE();
        __syncthreads();
        for (int i = tid; i < 1024; i += 256) {
            int n = i >> 4, dl = i & 15, d = j * 16 + dl;
            rh_s[n * 68 + d] = rst[n * 17 + dl] * h_s[n * 68 + d];
        }
        CLUSTER_WAIT();
        #pragma unroll
        for (int rr = 1; rr < 4; ++rr) {
            int rank = (j + rr) & 3;
            uint32_t rb = rbase[rank];
            for (int i = tid; i < 1024; i += 256) {
                int n = i >> 4, dl = i & 15, d = rank * 16 + dl;
                float r = ldc_f32(rb + (uint32_t)(n * 17 + dl) * 4);
                rh_s[n * 68 + d] = r * h_s[n * 68 + d];
            }
        }
        __syncthreads();

        {   // cand V-phase
            u64t acc[5][2];
            #pragma unroll
            for (int k = 0; k < 5; ++k) { acc[k][0] = acc[k][1] = 0; }
            const float* h0p = rh_s + rg * 68;
            const float* h1p = rh_s + (rg + 32) * 68;
            const float* wbase = wc_h + jg * 2;
            #pragma unroll 2
            for (int d4 = 0; d4 < 64; d4 += 4) {
                float4 hv0 = *(const float4*)(h0p + d4);
                float4 hv1 = *(const float4*)(h1p + d4);
                float h0a[4] = {hv0.x, hv0.y, hv0.z, hv0.w};
                float h1a[4] = {hv1.x, hv1.y, hv1.z, hv1.w};
                #pragma unroll
                for (int q = 0; q < 4; ++q) {
                    u64t a0 = pack_dup(h0a[q]);
                    u64t a1 = pack_dup(h1a[q]);
                    #pragma unroll
                    for (int k = 0; k < 5; ++k) {
                        u64t w = *(const u64t*)(wbase + k * 1024 + (d4 + q) * 16);
                        fma2(acc[k][0], a0, w);
                        fma2(acc[k][1], a1, w);
                    }
                }
            }
            #pragma unroll
            for (int k = 0; k < 5; ++k) {
                *(u64t*)(V_s + k * 2304 + rg * 36 + jg * 2)        = acc[k][0];
                *(u64t*)(V_s + k * 2304 + (rg + 32) * 36 + jg * 2) = acc[k][1];
            }
        }
        __syncthreads();

        {   // cand M-apply + GRU update
            float2 v0 = *(const float2*)(V_s + mg * 36 + ja2);
            float2 v1 = *(const float2*)(V_s + (mg + 32) * 36 + ja2);
            u64t y0 = pack2(cA.x + v0.x, cA.y + v0.y);
            u64t y1 = pack2(cB.x + v1.x, cB.y + v1.y);
            for (int k = 1; k < 5; ++k) {
                const float* Mk = Ms + (k - 1) * 4352;
                const float* Vk = V_s + k * 2304;
                #pragma unroll 4
                for (int m = 0; m < 64; m += 4) {
                    float4 mA = *(const float4*)(Mk + mg * 68 + m);
                    float4 mB = *(const float4*)(Mk + (mg + 32) * 68 + m);
                    float mAa[4] = {mA.x, mA.y, mA.z, mA.w};
                    float mBa[4] = {mB.x, mB.y, mB.z, mB.w};
                    #pragma unroll
                    for (int q = 0; q < 4; ++q) {
                        u64t v = *(const u64t*)(Vk + (m + q) * 36 + ja2);
                        fma2(y0, pack_dup(mAa[q]), v);
                        fma2(y1, pack_dup(mBa[q]), v);
                    }
                }
            }
            float* hout0 = d_out0 + ((size_t)(b * T_ + t)) * 4096;
            float2 cc0 = unpack2(y0), cc1 = unpack2(y1);
            float cand0[2] = {cc0.x, cc0.y};
            float cand1[2] = {cc1.x, cc1.y};
            #pragma unroll
            for (int q = 0; q < 2; ++q) {
                int cl = ja2 + q;
                int col = j * 16 + cl;
                float cv0 = tanh_f(cand0[q]);
                float ug0 = ugs[mg * 17 + cl];
                float hn0 = ug0 * h_s[mg * 68 + col] + (1.f - ug0) * cv0;
                hst[mg * 17 + cl] = hn0;
                float cv1 = tanh_f(cand1[q]);
                float ug1 = ugs[(mg + 32) * 17 + cl];
                float hn1 = ug1 * h_s[(mg + 32) * 68 + col] + (1.f - ug1) * cv1;
                hst[(mg + 32) * 17 + cl] = hn1;
                if (layer == 0) {
                    hout0[mg * 64 + col]        = hn0;
                    hout0[(mg + 32) * 64 + col] = hn1;
                } else if (t == idx_t) {
                    d_last[(size_t)b * 4096 + mg * 64 + col]        = hn0;
                    d_last[(size_t)b * 4096 + (mg + 32) * 64 + col] = hn1;
                }
            }
        }

        CLUSTER_ARRIVE();
        __syncthreads();
        for (int i = tid; i < 1024; i += 256) {
            int n = i >> 4, dl = i & 15;
            h_s[n * 68 + j * 16 + dl] = hst[n * 17 + dl];
        }
        CLUSTER_WAIT();
        #pragma unroll
        for (int rr = 1; rr < 4; ++rr) {
            int rank = (j + rr) & 3;
            uint32_t hb = hbase[rank];
            for (int i = tid; i < 1024; i += 256) {
                int n = i >> 4, dl = i & 15;
                h_s[n * 68 + rank * 16 + dl] = ldc_f32(hb + (uint32_t)(n * 17 + dl) * 4);
            }
        }
    }
    CLUSTER_SYNC();
}

// ---------------------------------------------------------------------------
__global__ void final_kernel(const float* __restrict__ Wp, const float* __restrict__ bp,
                             float* __restrict__ out)
{
    __shared__ float red[64 * 4];
    const int b = blockIdx.x, n = threadIdx.x;
    const float* h = d_last + (size_t)b * 4096 + n * 64;
    float l0 = bp[0], l1 = bp[1], l2 = bp[2], l3 = bp[3];
    #pragma unroll 8
    for (int d = 0; d < 64; ++d) {
        float v = fmaxf(h[d], 0.f);
        l0 += v * Wp[d * 4 + 0];
        l1 += v * Wp[d * 4 + 1];
        l2 += v * Wp[d * 4 + 2];
        l3 += v * Wp[d * 4 + 3];
    }
    red[n * 4 + 0] = l0; red[n * 4 + 1] = l1; red[n * 4 + 2] = l2; red[n * 4 + 3] = l3;
    __syncthreads();
    for (int s = 32; s > 0; s >>= 1) {
        if (n < s) {
            #pragma unroll
            for (int c = 0; c < 4; ++c)
                red[n * 4 + c] = fmaxf(red[n * 4 + c], red[(n + s) * 4 + c]);
        }
        __syncthreads();
    }
    if (n < 4) out[b * 4 + n] = red[n];
}

// ---------------------------------------------------------------------------
extern "C" void kernel_launch(void* const* d_in, const int* in_sizes, int n_in,
                              void* d_out, int out_size)
{
    (void)in_sizes; (void)n_in; (void)out_size;
    const float* X   = (const float*)d_in[0];
    const int*   len = (const int*)  d_in[1];
    const float* S0  = (const float*)d_in[2];
    const float* S1  = (const float*)d_in[3];
    const float* Wg0 = (const float*)d_in[4];
    const float* bg0 = (const float*)d_in[5];
    const float* Wc0 = (const float*)d_in[6];
    const float* bc0 = (const float*)d_in[7];
    const float* Wg1 = (const float*)d_in[8];
    const float* bg1 = (const float*)d_in[9];
    const float* Wc1 = (const float*)d_in[10];
    const float* bc1 = (const float*)d_in[11];
    const float* Wp  = (const float*)d_in[12];
    const float* bp  = (const float*)d_in[13];
    float* out = (float*)d_out;

    cudaFuncSetAttribute(pre_wmma,    cudaFuncAttributeMaxDynamicSharedMemorySize, PRE2_SMEM);
    cudaFuncSetAttribute(scan_kernel, cudaFuncAttributeMaxDynamicSharedMemorySize, SCAN_SMEM_BYTES);

    prep_kernel<<<2, 256>>>(S0, S1);
    prep_img<<<64, 256>>>(Wg0, Wc0, Wg1, Wc1);
    pre_wmma<<<B_ * T_, 256, PRE2_SMEM>>>(X, bg0, bc0, 0);
    scan_kernel<<<128, 256, SCAN_SMEM_BYTES>>>(Wg0, Wc0, len, 0);
    pre_wmma<<<B_ * T_, 256, PRE2_SMEM>>>(X, bg1, bc1, 1);
    scan_kernel<<<128, 256, SCAN_SMEM_BYTES>>>(Wg1, Wc1, len, 1);
    final_kernel<<<B_, 64>>>(Wp, bp, out);
}

// round 13
// speedup vs baseline: 1.3004x; 1.3004x over previous
#include <cuda_runtime.h>
#include <math.h>
#include <stdint.h>

#define B_ 32
#define T_ 128

typedef unsigned long long u64t;

// Scratch (device globals: allocation-free)
__device__ float d_M[4 * 4096];                 // S0, 2S0^2-I, S1, 2S1^2-I
__device__ float d_out0[B_ * T_ * 4096];        // layer-0 h states
__device__ float d_last[B_ * 4096];             // layer-1 h at last relevant t
__device__ float d_Gx[(size_t)B_ * T_ * 64 * 128]; // gate x-part preactivations (+bias)
__device__ float d_Cx[(size_t)B_ * T_ * 64 * 64];  // cand x-part preactivations (+bias)

// ---------------- f32x2 helpers ----------------
__device__ __forceinline__ u64t pack_dup(float x) {
    u64t r; asm("mov.b64 %0, {%1,%1};" : "=l"(r) : "f"(x)); return r;
}
__device__ __forceinline__ u64t pack2(float lo, float hi) {
    u64t r; asm("mov.b64 %0, {%1,%2};" : "=l"(r) : "f"(lo), "f"(hi)); return r;
}
__device__ __forceinline__ float2 unpack2(u64t v) {
    float2 f; asm("mov.b64 {%0,%1}, %2;" : "=f"(f.x), "=f"(f.y) : "l"(v)); return f;
}
__device__ __forceinline__ void fma2(u64t& d, u64t a, u64t b) {
    asm("fma.rn.f32x2 %0, %1, %2, %0;" : "+l"(d) : "l"(a), "l"(b));
}

__device__ __forceinline__ uint32_t s_u32(const void* p) {
    return (uint32_t)__cvta_generic_to_shared(p);
}
__device__ __forceinline__ uint32_t mapa_rank(uint32_t a, uint32_t r) {
    uint32_t o;
    asm("mapa.shared::cluster.u32 %0, %1, %2;" : "=r"(o) : "r"(a), "r"(r));
    return o;
}
__device__ __forceinline__ float ldc_f32(uint32_t a) {
    float v;
    asm volatile("ld.shared::cluster.f32 %0, [%1];" : "=f"(v) : "r"(a));
    return v;
}
__device__ __forceinline__ void cp16(float* dst, const float* src) {
    asm volatile("cp.async.cg.shared.global [%0], [%1], 16;"
                 :: "r"(s_u32(dst)), "l"(src));
}
#define CP_COMMIT() asm volatile("cp.async.commit_group;")
#define CP_WAIT1()  asm volatile("cp.async.wait_group 1;")
#define CLUSTER_ARRIVE() asm volatile("barrier.cluster.arrive.aligned;" ::: "memory")
#define CLUSTER_WAIT()   asm volatile("barrier.cluster.wait.aligned;"   ::: "memory")
#define CLUSTER_SYNC() do { CLUSTER_ARRIVE(); CLUSTER_WAIT(); } while (0)

__device__ __forceinline__ float sigmoid_f(float v) {
    return __fdividef(1.f, 1.f + __expf(-v));
}
__device__ __forceinline__ float tanh_f(float v) {
    return 1.f - __fdividef(2.f, __expf(2.f * v) + 1.f);
}

extern __shared__ float smem[];

// ---------------------------------------------------------------------------
// Precompute diffusion operators.
// ---------------------------------------------------------------------------
__global__ void prep_kernel(const float* __restrict__ S0, const float* __restrict__ S1)
{
    __shared__ float Ss[64 * 64];
    const int s = blockIdx.x;
    const float* S = s ? S1 : S0;
    for (int i = threadIdx.x; i < 4096; i += blockDim.x) Ss[i] = S[i];
    __syncthreads();
    for (int i = threadIdx.x; i < 4096; i += blockDim.x) {
        int m = i >> 6, n = i & 63;
        float acc = 0.f;
        #pragma unroll 8
        for (int p = 0; p < 64; ++p) acc += Ss[m * 64 + p] * Ss[p * 64 + n];
        d_M[(2 * s) * 4096 + i]     = Ss[i];
        d_M[(2 * s + 1) * 4096 + i] = 2.f * acc - (m == n ? 1.f : 0.f);
    }
}

// ---------------------------------------------------------------------------
// Precompute x-contributions for every (b,t). v5:
//  - A operands pair-interleaved [feat][(n&31)*2+(n>>5)] -> ONE LDS.64 yields
//    both row operands (n, n+32); conflict-free (lanes consecutive 8B).
//  - W_k double-buffered in SMEM via cp.async (unchanged).
// ---------------------------------------------------------------------------
#define PRE_SMEM_FLOATS 50048
#define PRE_SMEM_BYTES (PRE_SMEM_FLOATS * 4)

__global__ void __launch_bounds__(512, 1)
pre_kernel(const float* __restrict__ Xin,
           const float* __restrict__ Wg, const float* __restrict__ bg,
           const float* __restrict__ Wc, const float* __restrict__ bc,
           int layer)
{
    float* x_row = smem;             // [node][feat] pitch 68 (uniform vec reads)
    float* x_T   = smem + 4352;      // [feat][node-interleaved] pitch 66
    float* xa_T  = smem + 8576;      // 4 x [feat][node-interleaved] pitch 66
    float* M_T   = smem + 25472;     // phase1: 4 x [in][out-interleaved] pitch 66
    float* wbuf  = smem + 25472;     // phase2: 2 x 12288

    const int tid  = threadIdx.x;
    const int bt   = blockIdx.x;
    const int lane = tid & 31;
    const int g    = tid >> 5;

    const float* xsrc = (layer ? d_out0 : Xin) + (size_t)bt * 4096;

    for (int i = tid; i < 4096; i += 512) {
        int n = i >> 6, d = i & 63;
        float v = xsrc[i];
        x_row[n * 68 + d] = v;
        x_T[d * 66 + (n & 31) * 2 + (n >> 5)] = v;
    }
    for (int i = tid; i < 16384; i += 512) {
        int k = i >> 12, r = (i >> 6) & 63, c = i & 63;   // d_M[k][out=r][in=c]
        M_T[k * 4224 + c * 66 + (r & 31) * 2 + (r >> 5)] = d_M[i];
    }
    __syncthreads();

    // ---------------- phase 1: xa_k = M_k @ x ----------------
    {
        const int c4 = g * 4;
        #pragma unroll
        for (int k = 0; k < 4; ++k) {
            const float* MT = M_T + k * 4224;
            u64t a00 = 0, a01 = 0, a10 = 0, a11 = 0;
            #pragma unroll 4
            for (int p = 0; p < 64; ++p) {
                float2 mm = *(const float2*)(MT + p * 66 + lane * 2);   // rows lane,lane+32
                u64t d0 = pack_dup(mm.x);
                u64t d1 = pack_dup(mm.y);
                ulonglong2 xv = *(const ulonglong2*)(x_row + p * 68 + c4); // uniform
                fma2(a00, d0, xv.x); fma2(a01, d0, xv.y);
                fma2(a10, d1, xv.x); fma2(a11, d1, xv.y);
            }
            float* XT = xa_T + k * 4224;
            float2 v00 = unpack2(a00), v01 = unpack2(a01);
            float2 v10 = unpack2(a10), v11 = unpack2(a11);
            *(float2*)(XT + (c4 + 0) * 66 + lane * 2) = make_float2(v00.x, v10.x);
            *(float2*)(XT + (c4 + 1) * 66 + lane * 2) = make_float2(v00.y, v10.y);
            *(float2*)(XT + (c4 + 2) * 66 + lane * 2) = make_float2(v01.x, v11.x);
            *(float2*)(XT + (c4 + 3) * 66 + lane * 2) = make_float2(v01.y, v11.y);
        }
    }
    __syncthreads();   // M_T reads done -> wbuf may overwrite

    // ---------------- phase 2: Gx / Cx with cp.async'd W ----------------
    const int gb = g * 8;
    const int cb = g * 4;

    {
        float* wb = wbuf;
        for (int i = tid; i < 2048; i += 512) cp16(wb + i * 4, Wg + i * 4);
        for (int i = tid; i < 1024; i += 512) cp16(wb + 8192 + i * 4, Wc + i * 4);
        CP_COMMIT();
    }

    u64t ag0[4], ag1[4], ac0[2], ac1[2];
    #pragma unroll
    for (int q = 0; q < 4; ++q) {
        u64t bb = pack2(bg[gb + 2 * q], bg[gb + 2 * q + 1]);
        ag0[q] = bb; ag1[q] = bb;
    }
    #pragma unroll
    for (int q = 0; q < 2; ++q) {
        u64t bb = pack2(bc[cb + 2 * q], bc[cb + 2 * q + 1]);
        ac0[q] = bb; ac1[q] = bb;
    }

    #pragma unroll
    for (int k = 0; k < 5; ++k) {
        if (k < 4) {
            float* wb = wbuf + ((k + 1) & 1) * 12288;
            const float* wgk = Wg + (size_t)((k + 1) * 128) * 128;
            const float* wck = Wc + (size_t)((k + 1) * 128) * 64;
            for (int i = tid; i < 2048; i += 512) cp16(wb + i * 4, wgk + i * 4);
            for (int i = tid; i < 1024; i += 512) cp16(wb + 8192 + i * 4, wck + i * 4);
        }
        CP_COMMIT();
        CP_WAIT1();
        __syncthreads();

        const float* AT  = (k == 0) ? x_T : (xa_T + (k - 1) * 4224);
        const float* wgb = wbuf + (k & 1) * 12288 + gb;
        const float* wcb = wbuf + (k & 1) * 12288 + 8192 + cb;

        #pragma unroll 4
        for (int p = 0; p < 64; ++p) {
            float2 ap = *(const float2*)(AT + p * 66 + lane * 2);
            u64t a0 = pack_dup(ap.x);
            u64t a1 = pack_dup(ap.y);
            ulonglong2 w0 = *(const ulonglong2*)(wgb + p * 128);
            ulonglong2 w1 = *(const ulonglong2*)(wgb + p * 128 + 4);
            ulonglong2 wc = *(const ulonglong2*)(wcb + p * 64);
            fma2(ag0[0], a0, w0.x); fma2(ag0[1], a0, w0.y);
            fma2(ag0[2], a0, w1.x); fma2(ag0[3], a0, w1.y);
            fma2(ag1[0], a1, w0.x); fma2(ag1[1], a1, w0.y);
            fma2(ag1[2], a1, w1.x); fma2(ag1[3], a1, w1.y);
            fma2(ac0[0], a0, wc.x); fma2(ac0[1], a0, wc.y);
            fma2(ac1[0], a1, wc.x); fma2(ac1[1], a1, wc.y);
        }
        __syncthreads();
    }

    float* gx = d_Gx + (size_t)bt * 8192;
    float* cx = d_Cx + (size_t)bt * 4096;
    ulonglong2 s;
    s.x = ag0[0]; s.y = ag0[1]; *(ulonglong2*)(gx + lane * 128 + gb)          = s;
    s.x = ag0[2]; s.y = ag0[3]; *(ulonglong2*)(gx + lane * 128 + gb + 4)      = s;
    s.x = ag1[0]; s.y = ag1[1]; *(ulonglong2*)(gx + (lane + 32) * 128 + gb)     = s;
    s.x = ag1[2]; s.y = ag1[3]; *(ulonglong2*)(gx + (lane + 32) * 128 + gb + 4) = s;
    s.x = ac0[0]; s.y = ac0[1]; *(ulonglong2*)(cx + lane * 64 + cb)           = s;
    s.x = ac1[0]; s.y = ac1[1]; *(ulonglong2*)(cx + (lane + 32) * 64 + cb)      = s;
}

// ---------------------------------------------------------------------------
// Persistent per-layer scan (R9 512-thread d-split version) with MLP-batched
// DSMEM gathers in both exchanges.
// ---------------------------------------------------------------------------
#define SCAN_SMEM_BYTES (56256 * 4)

__global__ void __launch_bounds__(512, 1) __cluster_dims__(4, 1, 1)
scan_kernel(const float* __restrict__ Wg, const float* __restrict__ Wc,
            const int* __restrict__ lens, int layer)
{
    float* wg_h = smem;
    float* wc_h = smem + 10240;
    float* Ms   = smem + 15360;
    float* h_s  = smem + 32768;   // pitch 68
    float* rh_s = smem + 37120;   // pitch 68; also yP partial overlay
    float* V_s  = smem + 41472;   // 5 x 64 x 36
    float* rst  = smem + 52992;
    float* ugs  = smem + 54080;
    float* hst  = smem + 55168;
    float* yP   = rh_s;

    const int tid = threadIdx.x;
    const int b = blockIdx.x >> 2;
    const int j = blockIdx.x & 3;

    for (int i = tid; i < 10240; i += 512) {
        int k = i >> 11, d = (i >> 5) & 63, c = i & 31;
        int g = (c < 16) ? (j * 16 + c) : (64 + j * 16 + (c - 16));
        wg_h[i] = Wg[(size_t)(k * 128 + 64 + d) * 128 + g];
    }
    for (int i = tid; i < 5120; i += 512) {
        int k = i >> 10, d = (i >> 4) & 63, c = i & 15;
        wc_h[i] = Wc[(size_t)(k * 128 + 64 + d) * 64 + j * 16 + c];
    }
    for (int i = tid; i < 16384; i += 512) {
        int k = i >> 12, r = (i >> 6) & 63, p = i & 63;
        Ms[k * 4352 + r * 68 + p] = d_M[i];
    }
    for (int i = tid; i < 4096; i += 512)
        h_s[(i >> 6) * 68 + (i & 63)] = 0.f;

    int idx_t = lens[b] - 1;
    idx_t = idx_t < 0 ? 0 : (idx_t > T_ - 1 ? T_ - 1 : idx_t);

    uint32_t rbase[4], hbase[4];
    #pragma unroll
    for (int r = 0; r < 4; ++r) {
        rbase[r] = mapa_rank(s_u32(rst), (uint32_t)r);
        hbase[r] = mapa_rank(s_u32(hst), (uint32_t)r);
    }

    const int rg  = tid & 31;
    const int jg  = (tid >> 5) & 7;
    const int dh  = tid >> 8;
    const int s5  = tid & 255;
    const int mg  = s5 >> 3;
    const int ja4 = (s5 & 7) * 4;
    const int ja2 = (s5 & 7) * 2;
    const int g0  = (ja4 < 16) ? (j * 16 + ja4) : (64 + j * 16 + (ja4 - 16));
    const int c0  = j * 16 + ja2;
    const u64t ONE = pack_dup(1.f);
    // exchange indices: rows en0=tid>>4 (0..31) and en0+32, col edl=tid&15
    const int en0 = tid >> 4, edl = tid & 15;
    const uint32_t eoff0 = (uint32_t)(en0 * 17 + edl) * 4;
    const uint32_t eoff1 = (uint32_t)((en0 + 32) * 17 + edl) * 4;

    const float* gxb = d_Gx + (size_t)b * T_ * 8192;
    const float* cxb = d_Cx + (size_t)b * T_ * 4096;

    for (int t = 0; t < T_; ++t) {
        __syncthreads();

        float4 gA = make_float4(0.f, 0.f, 0.f, 0.f);
        float4 gB = gA;
        float2 cA = make_float2(0.f, 0.f);
        float2 cB = cA;
        if (dh == 0) {
            const float* gx = gxb + (size_t)t * 8192;
            const float* cx = cxb + (size_t)t * 4096;
            gA = __ldg((const float4*)(gx + mg * 128 + g0));
            gB = __ldg((const float4*)(gx + (mg + 32) * 128 + g0));
            cA = __ldg((const float2*)(cx + mg * 64 + c0));
            cB = __ldg((const float2*)(cx + (mg + 32) * 64 + c0));
        }

        // ---------- gate V-phase (d-split) ----------
        {
            u64t acc[5][4];
            #pragma unroll
            for (int k = 0; k < 5; ++k) { acc[k][0] = acc[k][1] = acc[k][2] = acc[k][3] = 0; }
            const float* h0p = h_s + rg * 68 + dh * 32;
            const float* h1p = h_s + (rg + 32) * 68 + dh * 32;
            const float* wbase = wg_h + jg * 4 + dh * 1024;
            #pragma unroll 2
            for (int d4 = 0; d4 < 32; d4 += 4) {
                float4 hv0 = *(const float4*)(h0p + d4);
                float4 hv1 = *(const float4*)(h1p + d4);
                float h0a[4] = {hv0.x, hv0.y, hv0.z, hv0.w};
                float h1a[4] = {hv1.x, hv1.y, hv1.z, hv1.w};
                #pragma unroll
                for (int q = 0; q < 4; ++q) {
                    u64t a0 = pack_dup(h0a[q]);
                    u64t a1 = pack_dup(h1a[q]);
                    #pragma unroll
                    for (int k = 0; k < 5; ++k) {
                        ulonglong2 w = *(const ulonglong2*)(wbase + k * 2048 + (d4 + q) * 32);
                        fma2(acc[k][0], a0, w.x); fma2(acc[k][1], a0, w.y);
                        fma2(acc[k][2], a1, w.x); fma2(acc[k][3], a1, w.y);
                    }
                }
            }
            if (dh == 0) {
                #pragma unroll
                for (int k = 0; k < 5; ++k) {
                    ulonglong2 sv;
                    sv.x = acc[k][0]; sv.y = acc[k][1];
                    *(ulonglong2*)(V_s + k * 2304 + rg * 36 + jg * 4) = sv;
                    sv.x = acc[k][2]; sv.y = acc[k][3];
                    *(ulonglong2*)(V_s + k * 2304 + (rg + 32) * 36 + jg * 4) = sv;
                }
            }
            __syncthreads();
            if (dh == 1) {
                #pragma unroll
                for (int k = 0; k < 5; ++k) {
                    float* p0 = V_s + k * 2304 + rg * 36 + jg * 4;
                    float* p1 = V_s + k * 2304 + (rg + 32) * 36 + jg * 4;
                    ulonglong2 c0v = *(ulonglong2*)p0;
                    ulonglong2 c1v = *(ulonglong2*)p1;
                    fma2(c0v.x, ONE, acc[k][0]); fma2(c0v.y, ONE, acc[k][1]);
                    fma2(c1v.x, ONE, acc[k][2]); fma2(c1v.y, ONE, acc[k][3]);
                    *(ulonglong2*)p0 = c0v;
                    *(ulonglong2*)p1 = c1v;
                }
            }
            __syncthreads();
        }

        // ---------- gate M-apply (k-split) + sigmoid + stage ----------
        {
            u64t y00, y01, y10, y11;
            if (dh == 0) {
                float4 vA = *(const float4*)(V_s + mg * 36 + ja4);
                float4 vB = *(const float4*)(V_s + (mg + 32) * 36 + ja4);
                y00 = pack2(gA.x + vA.x, gA.y + vA.y);
                y01 = pack2(gA.z + vA.z, gA.w + vA.w);
                y10 = pack2(gB.x + vB.x, gB.y + vB.y);
                y11 = pack2(gB.z + vB.z, gB.w + vB.w);
            } else {
                y00 = y01 = y10 = y11 = pack_dup(0.f);
            }
            const int kb = 1 + dh * 2;
            #pragma unroll
            for (int kk = 0; kk < 2; ++kk) {
                const float* Mk = Ms + (kb - 1 + kk) * 4352;
                const float* Vk = V_s + (kb + kk) * 2304;
                #pragma unroll 4
                for (int m = 0; m < 64; m += 4) {
                    float4 mA = *(const float4*)(Mk + mg * 68 + m);
                    float4 mB = *(const float4*)(Mk + (mg + 32) * 68 + m);
                    float mAa[4] = {mA.x, mA.y, mA.z, mA.w};
                    float mBa[4] = {mB.x, mB.y, mB.z, mB.w};
                    #pragma unroll
                    for (int q = 0; q < 4; ++q) {
                        ulonglong2 v = *(const ulonglong2*)(Vk + (m + q) * 36 + ja4);
                        u64t da = pack_dup(mAa[q]);
                        u64t db = pack_dup(mBa[q]);
                        fma2(y00, da, v.x); fma2(y01, da, v.y);
                        fma2(y10, db, v.x); fma2(y11, db, v.y);
                    }
                }
            }
            if (dh == 1) {
                ulonglong2 sv;
                sv.x = y00; sv.y = y01; *(ulonglong2*)(yP + s5 * 8)     = sv;
                sv.x = y10; sv.y = y11; *(ulonglong2*)(yP + s5 * 8 + 4) = sv;
            }
            __syncthreads();
            if (dh == 0) {
                ulonglong2 pa = *(const ulonglong2*)(yP + s5 * 8);
                ulonglong2 pb = *(const ulonglong2*)(yP + s5 * 8 + 4);
                fma2(y00, ONE, pa.x); fma2(y01, ONE, pa.y);
                fma2(y10, ONE, pb.x); fma2(y11, ONE, pb.y);
                float2 p00 = unpack2(y00), p01 = unpack2(y01);
                float2 p10 = unpack2(y10), p11 = unpack2(y11);
                float v0a[4] = {p00.x, p00.y, p01.x, p01.y};
                float v1a[4] = {p10.x, p10.y, p11.x, p11.y};
                #pragma unroll
                for (int q = 0; q < 4; ++q) {
                    int c = ja4 + q;
                    float s0 = sigmoid_f(v0a[q]);
                    float s1 = sigmoid_f(v1a[q]);
                    if (c < 16) { rst[mg * 17 + c] = s0;        rst[(mg + 32) * 17 + c] = s1; }
                    else        { ugs[mg * 17 + c - 16] = s0;   ugs[(mg + 32) * 17 + c - 16] = s1; }
                }
            }
            __syncthreads();
        }

        // r exchange: arrive, local quarter, wait, batched remote gather
        CLUSTER_ARRIVE();
        {
            int d = j * 16 + edl;
            rh_s[en0 * 68 + d]        = rst[en0 * 17 + edl] * h_s[en0 * 68 + d];
            rh_s[(en0 + 32) * 68 + d] = rst[(en0 + 32) * 17 + edl] * h_s[(en0 + 32) * 68 + d];
        }
        CLUSTER_WAIT();
        {
            float rv[3][2];
            #pragma unroll
            for (int rr = 1; rr < 4; ++rr) {
                uint32_t rb = rbase[(j + rr) & 3];
                rv[rr - 1][0] = ldc_f32(rb + eoff0);
                rv[rr - 1][1] = ldc_f32(rb + eoff1);
            }
            #pragma unroll
            for (int rr = 1; rr < 4; ++rr) {
                int d = ((j + rr) & 3) * 16 + edl;
                rh_s[en0 * 68 + d]        = rv[rr - 1][0] * h_s[en0 * 68 + d];
                rh_s[(en0 + 32) * 68 + d] = rv[rr - 1][1] * h_s[(en0 + 32) * 68 + d];
            }
        }
        __syncthreads();

        // ---------- cand V-phase (d-split) ----------
        {
            u64t acc[5][2];
            #pragma unroll
            for (int k = 0; k < 5; ++k) { acc[k][0] = acc[k][1] = 0; }
            const float* h0p = rh_s + rg * 68 + dh * 32;
            const float* h1p = rh_s + (rg + 32) * 68 + dh * 32;
            const float* wbase = wc_h + jg * 2 + dh * 512;
            #pragma unroll 2
            for (int d4 = 0; d4 < 32; d4 += 4) {
                float4 hv0 = *(const float4*)(h0p + d4);
                float4 hv1 = *(const float4*)(h1p + d4);
                float h0a[4] = {hv0.x, hv0.y, hv0.z, hv0.w};
                float h1a[4] = {hv1.x, hv1.y, hv1.z, hv1.w};
                #pragma unroll
                for (int q = 0; q < 4; ++q) {
                    u64t a0 = pack_dup(h0a[q]);
                    u64t a1 = pack_dup(h1a[q]);
                    #pragma unroll
                    for (int k = 0; k < 5; ++k) {
                        u64t w = *(const u64t*)(wbase + k * 1024 + (d4 + q) * 16);
                        fma2(acc[k][0], a0, w);
                        fma2(acc[k][1], a1, w);
                    }
                }
            }
            if (dh == 0) {
                #pragma unroll
                for (int k = 0; k < 5; ++k) {
                    *(u64t*)(V_s + k * 2304 + rg * 36 + jg * 2)        = acc[k][0];
                    *(u64t*)(V_s + k * 2304 + (rg + 32) * 36 + jg * 2) = acc[k][1];
                }
            }
            __syncthreads();
            if (dh == 1) {
                #pragma unroll
                for (int k = 0; k < 5; ++k) {
                    float* p0 = V_s + k * 2304 + rg * 36 + jg * 2;
                    float* p1 = V_s + k * 2304 + (rg + 32) * 36 + jg * 2;
                    u64t c0v = *(u64t*)p0;
                    u64t c1v = *(u64t*)p1;
                    fma2(c0v, ONE, acc[k][0]);
                    fma2(c1v, ONE, acc[k][1]);
                    *(u64t*)p0 = c0v;
                    *(u64t*)p1 = c1v;
                }
            }
            __syncthreads();
        }

        // ---------- cand M-apply (k-split) + GRU update ----------
        {
            u64t y0, y1;
            if (dh == 0) {
                float2 v0 = *(const float2*)(V_s + mg * 36 + ja2);
                float2 v1 = *(const float2*)(V_s + (mg + 32) * 36 + ja2);
                y0 = pack2(cA.x + v0.x, cA.y + v0.y);
                y1 = pack2(cB.x + v1.x, cB.y + v1.y);
            } else {
                y0 = y1 = pack_dup(0.f);
            }
            const int kb = 1 + dh * 2;
            #pragma unroll
            for (int kk = 0; kk < 2; ++kk) {
                const float* Mk = Ms + (kb - 1 + kk) * 4352;
                const float* Vk = V_s + (kb + kk) * 2304;
                #pragma unroll 4
                for (int m = 0; m < 64; m += 4) {
                    float4 mA = *(const float4*)(Mk + mg * 68 + m);
                    float4 mB = *(const float4*)(Mk + (mg + 32) * 68 + m);
                    float mAa[4] = {mA.x, mA.y, mA.z, mA.w};
                    float mBa[4] = {mB.x, mB.y, mB.z, mB.w};
                    #pragma unroll
                    for (int q = 0; q < 4; ++q) {
                        u64t v = *(const u64t*)(Vk + (m + q) * 36 + ja2);
                        fma2(y0, pack_dup(mAa[q]), v);
                        fma2(y1, pack_dup(mBa[q]), v);
                    }
                }
            }
            if (dh == 1) {
                *(u64t*)(yP + s5 * 4)     = y0;
                *(u64t*)(yP + s5 * 4 + 2) = y1;
            }
            __syncthreads();
            if (dh == 0) {
                u64t pa = *(const u64t*)(yP + s5 * 4);
                u64t pb = *(const u64t*)(yP + s5 * 4 + 2);
                fma2(y0, ONE, pa);
                fma2(y1, ONE, pb);
                float* hout0 = d_out0 + ((size_t)(b * T_ + t)) * 4096;
                float2 cc0 = unpack2(y0), cc1 = unpack2(y1);
                float cand0[2] = {cc0.x, cc0.y};
                float cand1[2] = {cc1.x, cc1.y};
                #pragma unroll
                for (int q = 0; q < 2; ++q) {
                    int cl = ja2 + q;
                    int col = j * 16 + cl;
                    float cv0 = tanh_f(cand0[q]);
                    float ug0 = ugs[mg * 17 + cl];
                    float hn0 = ug0 * h_s[mg * 68 + col] + (1.f - ug0) * cv0;
                    hst[mg * 17 + cl] = hn0;
                    float cv1 = tanh_f(cand1[q]);
                    float ug1 = ugs[(mg + 32) * 17 + cl];
                    float hn1 = ug1 * h_s[(mg + 32) * 68 + col] + (1.f - ug1) * cv1;
                    hst[(mg + 32) * 17 + cl] = hn1;
                    if (layer == 0) {
                        hout0[mg * 64 + col]        = hn0;
                        hout0[(mg + 32) * 64 + col] = hn1;
                    } else if (t == idx_t) {
                        d_last[(size_t)b * 4096 + mg * 64 + col]        = hn0;
                        d_last[(size_t)b * 4096 + (mg + 32) * 64 + col] = hn1;
                    }
                }
            }
            __syncthreads();
        }

        // h exchange: arrive, local quarter, wait, batched remote gather
        CLUSTER_ARRIVE();
        {
            h_s[en0 * 68 + j * 16 + edl]        = hst[en0 * 17 + edl];
            h_s[(en0 + 32) * 68 + j * 16 + edl] = hst[(en0 + 32) * 17 + edl];
        }
        CLUSTER_WAIT();
        {
            float hv[3][2];
            #pragma unroll
            for (int rr = 1; rr < 4; ++rr) {
                uint32_t hb = hbase[(j + rr) & 3];
                hv[rr - 1][0] = ldc_f32(hb + eoff0);
                hv[rr - 1][1] = ldc_f32(hb + eoff1);
            }
            #pragma unroll
            for (int rr = 1; rr < 4; ++rr) {
                int d = ((j + rr) & 3) * 16 + edl;
                h_s[en0 * 68 + d]        = hv[rr - 1][0];
                h_s[(en0 + 32) * 68 + d] = hv[rr - 1][1];
            }
        }
    }
    CLUSTER_SYNC();
}

// ---------------------------------------------------------------------------
__global__ void final_kernel(const float* __restrict__ Wp, const float* __restrict__ bp,
                             float* __restrict__ out)
{
    __shared__ float red[64 * 4];
    const int b = blockIdx.x, n = threadIdx.x;
    const float* h = d_last + (size_t)b * 4096 + n * 64;
    float l0 = bp[0], l1 = bp[1], l2 = bp[2], l3 = bp[3];
    #pragma unroll 8
    for (int d = 0; d < 64; ++d) {
        float v = fmaxf(h[d], 0.f);
        l0 += v * Wp[d * 4 + 0];
        l1 += v * Wp[d * 4 + 1];
        l2 += v * Wp[d * 4 + 2];
        l3 += v * Wp[d * 4 + 3];
    }
    red[n * 4 + 0] = l0; red[n * 4 + 1] = l1; red[n * 4 + 2] = l2; red[n * 4 + 3] = l3;
    __syncthreads();
    for (int s = 32; s > 0; s >>= 1) {
        if (n < s) {
            #pragma unroll
            for (int c = 0; c < 4; ++c)
                red[n * 4 + c] = fmaxf(red[n * 4 + c], red[(n + s) * 4 + c]);
        }
        __syncthreads();
    }
    if (n < 4) out[b * 4 + n] = red[n];
}

// ---------------------------------------------------------------------------
extern "C" void kernel_launch(void* const* d_in, const int* in_sizes, int n_in,
                              void* d_out, int out_size)
{
    (void)in_sizes; (void)n_in; (void)out_size;
    const float* X   = (const float*)d_in[0];
    const int*   len = (const int*)  d_in[1];
    const float* S0  = (const float*)d_in[2];
    const float* S1  = (const float*)d_in[3];
    const float* Wg0 = (const float*)d_in[4];
    const float* bg0 = (const float*)d_in[5];
    const float* Wc0 = (const float*)d_in[6];
    const float* bc0 = (const float*)d_in[7];
    const float* Wg1 = (const float*)d_in[8];
    const float* bg1 = (const float*)d_in[9];
    const float* Wc1 = (const float*)d_in[10];
    const float* bc1 = (const float*)d_in[11];
    const float* Wp  = (const float*)d_in[12];
    const float* bp  = (const float*)d_in[13];
    float* out = (float*)d_out;

    cudaFuncSetAttribute(pre_kernel,  cudaFuncAttributeMaxDynamicSharedMemorySize, PRE_SMEM_BYTES);
    cudaFuncSetAttribute(scan_kernel, cudaFuncAttributeMaxDynamicSharedMemorySize, SCAN_SMEM_BYTES);

    prep_kernel<<<2, 256>>>(S0, S1);
    pre_kernel<<<B_ * T_, 512, PRE_SMEM_BYTES>>>(X, Wg0, bg0, Wc0, bc0, 0);
    scan_kernel<<<128, 512, SCAN_SMEM_BYTES>>>(Wg0, Wc0, len, 0);
    pre_kernel<<<B_ * T_, 512, PRE_SMEM_BYTES>>>(X, Wg1, bg1, Wc1, bc1, 1);
    scan_kernel<<<128, 512, SCAN_SMEM_BYTES>>>(Wg1, Wc1, len, 1);
    final_kernel<<<B_, 64>>>(Wp, bp, out);
}

// round 14
// speedup vs baseline: 1.3756x; 1.0579x over previous
#include <cuda_runtime.h>
#include <cuda_bf16.h>
#include <mma.h>
#include <math.h>
#include <stdint.h>

using namespace nvcuda;

#define B_ 32
#define T_ 128

typedef unsigned long long u64t;

// ---------------- device globals ----------------
__device__ float d_M[4 * 4096];
__device__ float d_out0[B_ * T_ * 4096];
__device__ float d_last[B_ * 4096];
__device__ float d_Gx[(size_t)B_ * T_ * 64 * 128];
__device__ float d_Cx[(size_t)B_ * T_ * 64 * 64];
__device__ __align__(16) unsigned char d_MI[2 * 32768];      // [prec][256x64 bf16] dense
__device__ __align__(16) unsigned char d_WI[2 * 2 * 122880]; // [layer][prec][320x192 bf16] dense

// ---------------- helpers ----------------
__device__ __forceinline__ u64t pack_dup(float x) {
    u64t r; asm("mov.b64 %0, {%1,%1};" : "=l"(r) : "f"(x)); return r;
}
__device__ __forceinline__ u64t pack2(float lo, float hi) {
    u64t r; asm("mov.b64 %0, {%1,%2};" : "=l"(r) : "f"(lo), "f"(hi)); return r;
}
__device__ __forceinline__ float2 unpack2(u64t v) {
    float2 f; asm("mov.b64 {%0,%1}, %2;" : "=f"(f.x), "=f"(f.y) : "l"(v)); return f;
}
__device__ __forceinline__ void fma2(u64t& d, u64t a, u64t b) {
    asm("fma.rn.f32x2 %0, %1, %2, %0;" : "+l"(d) : "l"(a), "l"(b));
}
__device__ __forceinline__ uint32_t s_u32(const void* p) {
    return (uint32_t)__cvta_generic_to_shared(p);
}
__device__ __forceinline__ uint32_t mapa_rank(uint32_t a, uint32_t r) {
    uint32_t o;
    asm("mapa.shared::cluster.u32 %0, %1, %2;" : "=r"(o) : "r"(a), "r"(r));
    return o;
}
__device__ __forceinline__ float ldc_f32(uint32_t a) {
    float v;
    asm volatile("ld.shared::cluster.f32 %0, [%1];" : "=f"(v) : "r"(a));
    return v;
}
__device__ __forceinline__ void cp16(void* dst, const void* src) {
    asm volatile("cp.async.cg.shared.global [%0], [%1], 16;"
                 :: "r"(s_u32(dst)), "l"(src));
}
#define CP_COMMIT() asm volatile("cp.async.commit_group;")
#define CP_WAIT0()  asm volatile("cp.async.wait_group 0;")
#define CP_WAIT1()  asm volatile("cp.async.wait_group 1;")
#define CLUSTER_ARRIVE() asm volatile("barrier.cluster.arrive.aligned;" ::: "memory")
#define CLUSTER_WAIT()   asm volatile("barrier.cluster.wait.aligned;"   ::: "memory")
#define CLUSTER_SYNC() do { CLUSTER_ARRIVE(); CLUSTER_WAIT(); } while (0)

__device__ __forceinline__ float sigmoid_f(float v) {
    return __fdividef(1.f, 1.f + __expf(-v));
}
__device__ __forceinline__ float tanh_f(float v) {
    return 1.f - __fdividef(2.f, __expf(2.f * v) + 1.f);
}

extern __shared__ float smem[];

// ---------------------------------------------------------------------------
__global__ void prep_kernel(const float* __restrict__ S0, const float* __restrict__ S1)
{
    __shared__ float Ss[64 * 64];
    const int s = blockIdx.x;
    const float* S = s ? S1 : S0;
    for (int i = threadIdx.x; i < 4096; i += blockDim.x) Ss[i] = S[i];
    __syncthreads();
    for (int i = threadIdx.x; i < 4096; i += blockDim.x) {
        int m = i >> 6, n = i & 63;
        float acc = 0.f;
        #pragma unroll 8
        for (int p = 0; p < 64; ++p) acc += Ss[m * 64 + p] * Ss[p * 64 + n];
        d_M[(2 * s) * 4096 + i]     = Ss[i];
        d_M[(2 * s + 1) * 4096 + i] = 2.f * acc - (m == n ? 1.f : 0.f);
    }
}

// ---------------------------------------------------------------------------
// bf16 hi/lo dense operand images.
// MI[np][n], np=k*64+m = M_k[m][n].  WI[kcat][c], kcat=kt*64+kk:
//   c<128 -> Wg[kt*128+kk][c], else Wc[kt*128+kk][c-128].
// ---------------------------------------------------------------------------
__global__ void prep_img(const float* __restrict__ Wg0, const float* __restrict__ Wc0,
                         const float* __restrict__ Wg1, const float* __restrict__ Wc1)
{
    const int gt = blockIdx.x * blockDim.x + threadIdx.x;
    const int gs = gridDim.x * blockDim.x;
    for (int i = gt; i < 16384; i += gs) {
        int np = i >> 6, n = i & 63;
        float v = d_M[(np >> 6) * 4096 + (np & 63) * 64 + n];
        __nv_bfloat16 hi = __float2bfloat16(v);
        __nv_bfloat16 lo = __float2bfloat16(v - __bfloat162float(hi));
        *(__nv_bfloat16*)(d_MI + np * 128 + n * 2) = hi;
        *(__nv_bfloat16*)(d_MI + 32768 + np * 128 + n * 2) = lo;
    }
    for (int i = gt; i < 2 * 61440; i += gs) {
        int l = i / 61440, rem = i % 61440;
        int kcat = rem / 192, c = rem % 192;
        int kt = kcat >> 6, kk = kcat & 63;
        float v;
        if (c < 128) v = (l ? Wg1 : Wg0)[(size_t)(kt * 128 + kk) * 128 + c];
        else         v = (l ? Wc1 : Wc0)[(size_t)(kt * 128 + kk) * 64 + (c - 128)];
        __nv_bfloat16 hi = __float2bfloat16(v);
        __nv_bfloat16 lo = __float2bfloat16(v - __bfloat162float(hi));
        unsigned char* base = d_WI + l * 245760;
        *(__nv_bfloat16*)(base + kcat * 384 + c * 2) = hi;
        *(__nv_bfloat16*)(base + 122880 + kcat * 384 + c * 2) = lo;
    }
}

// ---------------------------------------------------------------------------
// WMMA precompute of Gx/Cx with conflict-free padded pitches + double-buffered W.
// One (b,t) per CTA, 8 warps. Pitches (bytes mod 128): A 656->16, W 400->16,
// M 144->16, S1 288->32, S2 800->32 — all conflict-free for ldmatrix/stores.
// smem: A2h [0,41984) 64x328 bf16 | A2l [41984,83968) | SCR [83968, +102400)
//   SCR phase1: Mh 36864 + Ml 36864 -> then fp32 S 256x72
//   SCR phase2: wbuf[2] x (hi 64x200 + lo 64x200) = 2x51200 -> then fp32 S 64x200
// ---------------------------------------------------------------------------
#define PRE2_SMEM (83968 + 102400)

__global__ void __launch_bounds__(256, 1)
pre_wmma(const float* __restrict__ Xin, const float* __restrict__ bg,
         const float* __restrict__ bc, int layer)
{
    unsigned char* sm  = (unsigned char*)smem;
    __nv_bfloat16* A2h = (__nv_bfloat16*)sm;
    __nv_bfloat16* A2l = (__nv_bfloat16*)(sm + 41984);
    unsigned char* SCR = sm + 83968;

    const int tid = threadIdx.x;
    const int w = tid >> 5;
    const int bt = blockIdx.x;

    // M images -> SCR (pitch 144B); x -> A2 tile0 (pitch 328 elems)
    for (int i = tid; i < 4096; i += 256) {
        int prec = i >> 11, r2 = i & 2047, row = r2 >> 3, c = r2 & 7;
        cp16(SCR + prec * 36864 + row * 144 + c * 16,
             d_MI + prec * 32768 + row * 128 + c * 16);
    }
    CP_COMMIT();
    const float* xsrc = (layer ? d_out0 : Xin) + (size_t)bt * 4096;
    for (int i = tid; i < 4096; i += 256) {
        int n = i >> 6, f = i & 63;
        float v = xsrc[i];
        __nv_bfloat16 hi = __float2bfloat16(v);
        __nv_bfloat16 lo = __float2bfloat16(v - __bfloat162float(hi));
        A2h[n * 328 + f] = hi;
        A2l[n * 328 + f] = lo;
    }
    CP_WAIT0();
    __syncthreads();

    // ---------------- phase 1: xa = M_stack(256x64) @ x(64x64) ----------------
    {
        wmma::fragment<wmma::accumulator, 16, 16, 16, float> acc1[8];
        #pragma unroll
        for (int i = 0; i < 8; ++i) wmma::fill_fragment(acc1[i], 0.f);
        const __nv_bfloat16* Mh = (const __nv_bfloat16*)SCR;
        const __nv_bfloat16* Ml = (const __nv_bfloat16*)(SCR + 36864);
        #pragma unroll
        for (int ks = 0; ks < 4; ++ks) {
            wmma::fragment<wmma::matrix_a, 16, 16, 16, __nv_bfloat16, wmma::row_major> ah[2], al[2];
            wmma::fragment<wmma::matrix_b, 16, 16, 16, __nv_bfloat16, wmma::row_major> bh[4], bl[4];
            #pragma unroll
            for (int mi = 0; mi < 2; ++mi) {
                wmma::load_matrix_sync(ah[mi], Mh + (w * 2 + mi) * 16 * 72 + ks * 16, 72);
                wmma::load_matrix_sync(al[mi], Ml + (w * 2 + mi) * 16 * 72 + ks * 16, 72);
            }
            #pragma unroll
            for (int nt = 0; nt < 4; ++nt) {
                wmma::load_matrix_sync(bh[nt], A2h + ks * 16 * 328 + nt * 16, 328);
                wmma::load_matrix_sync(bl[nt], A2l + ks * 16 * 328 + nt * 16, 328);
            }
            #pragma unroll
            for (int mi = 0; mi < 2; ++mi)
                #pragma unroll
                for (int nt = 0; nt < 4; ++nt) {
                    int x = mi * 4 + nt;
                    wmma::mma_sync(acc1[x], ah[mi], bh[nt], acc1[x]);
                    wmma::mma_sync(acc1[x], al[mi], bh[nt], acc1[x]);
                    wmma::mma_sync(acc1[x], ah[mi], bl[nt], acc1[x]);
                }
        }
        __syncthreads();                     // M reads done -> S may overwrite
        float* S = (float*)SCR;              // 256 x 72 fp32
        #pragma unroll
        for (int mi = 0; mi < 2; ++mi)
            #pragma unroll
            for (int nt = 0; nt < 4; ++nt)
                wmma::store_matrix_sync(S + (w * 2 + mi) * 16 * 72 + nt * 16,
                                        acc1[mi * 4 + nt], 72, wmma::mem_row_major);
        __syncthreads();
        for (int i = tid; i < 16384; i += 256) {
            int row = i >> 6, f = i & 63;
            int k = row >> 6, m = row & 63;
            float v = S[row * 72 + f];
            __nv_bfloat16 hi = __float2bfloat16(v);
            __nv_bfloat16 lo = __float2bfloat16(v - __bfloat162float(hi));
            A2h[m * 328 + (k + 1) * 64 + f] = hi;
            A2l[m * 328 + (k + 1) * 64 + f] = lo;
        }
        __syncthreads();
    }

    // ---------------- phase 2: [x|xa](64x320) @ WI(320x192) ----------------
    {
        wmma::fragment<wmma::accumulator, 16, 16, 16, float> acc2[6];
        #pragma unroll
        for (int i = 0; i < 6; ++i) wmma::fill_fragment(acc2[i], 0.f);
        const int mt = w >> 1, ng = w & 1;
        const unsigned char* gW = d_WI + layer * 245760;

        // prefetch kt=0 into buf 0 (dst pitch 400B)
        {
            unsigned char* dst = SCR;
            for (int i = tid; i < 1536; i += 256) {
                int row = i / 24, c = i % 24;
                cp16(dst + row * 400 + c * 16, gW + row * 384 + c * 16);
                cp16(dst + 25600 + row * 400 + c * 16, gW + 122880 + row * 384 + c * 16);
            }
            CP_COMMIT();
        }

        for (int kt = 0; kt < 5; ++kt) {
            if (kt < 4) {
                unsigned char* dst = SCR + ((kt + 1) & 1) * 51200;
                const unsigned char* srcH = gW + (kt + 1) * 24576;
                const unsigned char* srcL = gW + 122880 + (kt + 1) * 24576;
                for (int i = tid; i < 1536; i += 256) {
                    int row = i / 24, c = i % 24;
                    cp16(dst + row * 400 + c * 16, srcH + row * 384 + c * 16);
                    cp16(dst + 25600 + row * 400 + c * 16, srcL + row * 384 + c * 16);
                }
            }
            CP_COMMIT();
            CP_WAIT1();
            __syncthreads();

            const __nv_bfloat16* WbH = (const __nv_bfloat16*)(SCR + (kt & 1) * 51200);
            const __nv_bfloat16* WbL = (const __nv_bfloat16*)(SCR + (kt & 1) * 51200 + 25600);
            #pragma unroll
            for (int ks = 0; ks < 4; ++ks) {
                wmma::fragment<wmma::matrix_a, 16, 16, 16, __nv_bfloat16, wmma::row_major> ah, al;
                wmma::load_matrix_sync(ah, A2h + mt * 16 * 328 + kt * 64 + ks * 16, 328);
                wmma::load_matrix_sync(al, A2l + mt * 16 * 328 + kt * 64 + ks * 16, 328);
                #pragma unroll
                for (int nt = 0; nt < 6; ++nt) {
                    wmma::fragment<wmma::matrix_b, 16, 16, 16, __nv_bfloat16, wmma::row_major> bh, bl;
                    int nc = (ng * 6 + nt) * 16;
                    wmma::load_matrix_sync(bh, WbH + ks * 16 * 200 + nc, 200);
                    wmma::load_matrix_sync(bl, WbL + ks * 16 * 200 + nc, 200);
                    wmma::mma_sync(acc2[nt], ah, bh, acc2[nt]);
                    wmma::mma_sync(acc2[nt], al, bh, acc2[nt]);
                    wmma::mma_sync(acc2[nt], ah, bl, acc2[nt]);
                }
            }
            __syncthreads();   // buf reads done before reuse
        }

        float* S = (float*)SCR;              // 64 x 200 fp32
        #pragma unroll
        for (int nt = 0; nt < 6; ++nt)
            wmma::store_matrix_sync(S + mt * 16 * 200 + (ng * 6 + nt) * 16,
                                    acc2[nt], 200, wmma::mem_row_major);
        __syncthreads();
        for (int i = tid; i < 12288; i += 256) {
            int n = i / 192, c = i % 192;
            float v = S[n * 200 + c];
            if (c < 128) d_Gx[(size_t)bt * 8192 + n * 128 + c] = v + bg[c];
            else         d_Cx[(size_t)bt * 4096 + n * 64 + (c - 128)] = v + bc[c - 128];
        }
    }
}

// ---------------------------------------------------------------------------
// Persistent per-layer scan — R13 512-thread d-split + batched DSMEM gathers.
// ---------------------------------------------------------------------------
#define SCAN_SMEM_BYTES (56256 * 4)

__global__ void __launch_bounds__(512, 1) __cluster_dims__(4, 1, 1)
scan_kernel(const float* __restrict__ Wg, const float* __restrict__ Wc,
            const int* __restrict__ lens, int layer)
{
    float* wg_h = smem;
    float* wc_h = smem + 10240;
    float* Ms   = smem + 15360;
    float* h_s  = smem + 32768;
    float* rh_s = smem + 37120;
    float* V_s  = smem + 41472;
    float* rst  = smem + 52992;
    float* ugs  = smem + 54080;
    float* hst  = smem + 55168;
    float* yP   = rh_s;

    const int tid = threadIdx.x;
    const int b = blockIdx.x >> 2;
    const int j = blockIdx.x & 3;

    for (int i = tid; i < 10240; i += 512) {
        int k = i >> 11, d = (i >> 5) & 63, c = i & 31;
        int g = (c < 16) ? (j * 16 + c) : (64 + j * 16 + (c - 16));
        wg_h[i] = Wg[(size_t)(k * 128 + 64 + d) * 128 + g];
    }
    for (int i = tid; i < 5120; i += 512) {
        int k = i >> 10, d = (i >> 4) & 63, c = i & 15;
        wc_h[i] = Wc[(size_t)(k * 128 + 64 + d) * 64 + j * 16 + c];
    }
    for (int i = tid; i < 16384; i += 512) {
        int k = i >> 12, r = (i >> 6) & 63, p = i & 63;
        Ms[k * 4352 + r * 68 + p] = d_M[i];
    }
    for (int i = tid; i < 4096; i += 512)
        h_s[(i >> 6) * 68 + (i & 63)] = 0.f;

    int idx_t = lens[b] - 1;
    idx_t = idx_t < 0 ? 0 : (idx_t > T_ - 1 ? T_ - 1 : idx_t);

    uint32_t rbase[4], hbase[4];
    #pragma unroll
    for (int r = 0; r < 4; ++r) {
        rbase[r] = mapa_rank(s_u32(rst), (uint32_t)r);
        hbase[r] = mapa_rank(s_u32(hst), (uint32_t)r);
    }

    const int rg  = tid & 31;
    const int jg  = (tid >> 5) & 7;
    const int dh  = tid >> 8;
    const int s5  = tid & 255;
    const int mg  = s5 >> 3;
    const int ja4 = (s5 & 7) * 4;
    const int ja2 = (s5 & 7) * 2;
    const int g0  = (ja4 < 16) ? (j * 16 + ja4) : (64 + j * 16 + (ja4 - 16));
    const int c0  = j * 16 + ja2;
    const u64t ONE = pack_dup(1.f);
    const int en0 = tid >> 4, edl = tid & 15;
    const uint32_t eoff0 = (uint32_t)(en0 * 17 + edl) * 4;
    const uint32_t eoff1 = (uint32_t)((en0 + 32) * 17 + edl) * 4;

    const float* gxb = d_Gx + (size_t)b * T_ * 8192;
    const float* cxb = d_Cx + (size_t)b * T_ * 4096;

    for (int t = 0; t < T_; ++t) {
        __syncthreads();

        float4 gA = make_float4(0.f, 0.f, 0.f, 0.f);
        float4 gB = gA;
        float2 cA = make_float2(0.f, 0.f);
        float2 cB = cA;
        if (dh == 0) {
            const float* gx = gxb + (size_t)t * 8192;
            const float* cx = cxb + (size_t)t * 4096;
            gA = __ldg((const float4*)(gx + mg * 128 + g0));
            gB = __ldg((const float4*)(gx + (mg + 32) * 128 + g0));
            cA = __ldg((const float2*)(cx + mg * 64 + c0));
            cB = __ldg((const float2*)(cx + (mg + 32) * 64 + c0));
        }

        {   // gate V-phase (d-split)
            u64t acc[5][4];
            #pragma unroll
            for (int k = 0; k < 5; ++k) { acc[k][0] = acc[k][1] = acc[k][2] = acc[k][3] = 0; }
            const float* h0p = h_s + rg * 68 + dh * 32;
            const float* h1p = h_s + (rg + 32) * 68 + dh * 32;
            const float* wbase = wg_h + jg * 4 + dh * 1024;
            #pragma unroll 2
            for (int d4 = 0; d4 < 32; d4 += 4) {
                float4 hv0 = *(const float4*)(h0p + d4);
                float4 hv1 = *(const float4*)(h1p + d4);
                float h0a[4] = {hv0.x, hv0.y, hv0.z, hv0.w};
                float h1a[4] = {hv1.x, hv1.y, hv1.z, hv1.w};
                #pragma unroll
                for (int q = 0; q < 4; ++q) {
                    u64t a0 = pack_dup(h0a[q]);
                    u64t a1 = pack_dup(h1a[q]);
                    #pragma unroll
                    for (int k = 0; k < 5; ++k) {
                        ulonglong2 w = *(const ulonglong2*)(wbase + k * 2048 + (d4 + q) * 32);
                        fma2(acc[k][0], a0, w.x); fma2(acc[k][1], a0, w.y);
                        fma2(acc[k][2], a1, w.x); fma2(acc[k][3], a1, w.y);
                    }
                }
            }
            if (dh == 0) {
                #pragma unroll
                for (int k = 0; k < 5; ++k) {
                    ulonglong2 sv;
                    sv.x = acc[k][0]; sv.y = acc[k][1];
                    *(ulonglong2*)(V_s + k * 2304 + rg * 36 + jg * 4) = sv;
                    sv.x = acc[k][2]; sv.y = acc[k][3];
                    *(ulonglong2*)(V_s + k * 2304 + (rg + 32) * 36 + jg * 4) = sv;
                }
            }
            __syncthreads();
            if (dh == 1) {
                #pragma unroll
                for (int k = 0; k < 5; ++k) {
                    float* p0 = V_s + k * 2304 + rg * 36 + jg * 4;
                    float* p1 = V_s + k * 2304 + (rg + 32) * 36 + jg * 4;
                    ulonglong2 c0v = *(ulonglong2*)p0;
                    ulonglong2 c1v = *(ulonglong2*)p1;
                    fma2(c0v.x, ONE, acc[k][0]); fma2(c0v.y, ONE, acc[k][1]);
                    fma2(c1v.x, ONE, acc[k][2]); fma2(c1v.y, ONE, acc[k][3]);
                    *(ulonglong2*)p0 = c0v;
                    *(ulonglong2*)p1 = c1v;
                }
            }
            __syncthreads();
        }

        {   // gate M-apply (k-split) + sigmoid + stage
            u64t y00, y01, y10, y11;
            if (dh == 0) {
                float4 vA = *(const float4*)(V_s + mg * 36 + ja4);
                float4 vB = *(const float4*)(V_s + (mg + 32) * 36 + ja4);
                y00 = pack2(gA.x + vA.x, gA.y + vA.y);
                y01 = pack2(gA.z + vA.z, gA.w + vA.w);
                y10 = pack2(gB.x + vB.x, gB.y + vB.y);
                y11 = pack2(gB.z + vB.z, gB.w + vB.w);
            } else {
                y00 = y01 = y10 = y11 = pack_dup(0.f);
            }
            const int kb = 1 + dh * 2;
            #pragma unroll
            for (int kk = 0; kk < 2; ++kk) {
                const float* Mk = Ms + (kb - 1 + kk) * 4352;
                const float* Vk = V_s + (kb + kk) * 2304;
                #pragma unroll 4
                for (int m = 0; m < 64; m += 4) {
                    float4 mA = *(const float4*)(Mk + mg * 68 + m);
                    float4 mB = *(const float4*)(Mk + (mg + 32) * 68 + m);
                    float mAa[4] = {mA.x, mA.y, mA.z, mA.w};
                    float mBa[4] = {mB.x, mB.y, mB.z, mB.w};
                    #pragma unroll
                    for (int q = 0; q < 4; ++q) {
                        ulonglong2 v = *(const ulonglong2*)(Vk + (m + q) * 36 + ja4);
                        u64t da = pack_dup(mAa[q]);
                        u64t db = pack_dup(mBa[q]);
                        fma2(y00, da, v.x); fma2(y01, da, v.y);
                        fma2(y10, db, v.x); fma2(y11, db, v.y);
                    }
                }
            }
            if (dh == 1) {
                ulonglong2 sv;
                sv.x = y00; sv.y = y01; *(ulonglong2*)(yP + s5 * 8)     = sv;
                sv.x = y10; sv.y = y11; *(ulonglong2*)(yP + s5 * 8 + 4) = sv;
            }
            __syncthreads();
            if (dh == 0) {
                ulonglong2 pa = *(const ulonglong2*)(yP + s5 * 8);
                ulonglong2 pb = *(const ulonglong2*)(yP + s5 * 8 + 4);
                fma2(y00, ONE, pa.x); fma2(y01, ONE, pa.y);
                fma2(y10, ONE, pb.x); fma2(y11, ONE, pb.y);
                float2 p00 = unpack2(y00), p01 = unpack2(y01);
                float2 p10 = unpack2(y10), p11 = unpack2(y11);
                float v0a[4] = {p00.x, p00.y, p01.x, p01.y};
                float v1a[4] = {p10.x, p10.y, p11.x, p11.y};
                #pragma unroll
                for (int q = 0; q < 4; ++q) {
                    int c = ja4 + q;
                    float s0 = sigmoid_f(v0a[q]);
                    float s1 = sigmoid_f(v1a[q]);
                    if (c < 16) { rst[mg * 17 + c] = s0;        rst[(mg + 32) * 17 + c] = s1; }
                    else        { ugs[mg * 17 + c - 16] = s0;   ugs[(mg + 32) * 17 + c - 16] = s1; }
                }
            }
            __syncthreads();
        }

        // r exchange
        CLUSTER_ARRIVE();
        {
            int d = j * 16 + edl;
            rh_s[en0 * 68 + d]        = rst[en0 * 17 + edl] * h_s[en0 * 68 + d];
            rh_s[(en0 + 32) * 68 + d] = rst[(en0 + 32) * 17 + edl] * h_s[(en0 + 32) * 68 + d];
        }
        CLUSTER_WAIT();
        {
            float rv[3][2];
            #pragma unroll
            for (int rr = 1; rr < 4; ++rr) {
                uint32_t rb = rbase[(j + rr) & 3];
                rv[rr - 1][0] = ldc_f32(rb + eoff0);
                rv[rr - 1][1] = ldc_f32(rb + eoff1);
            }
            #pragma unroll
            for (int rr = 1; rr < 4; ++rr) {
                int d = ((j + rr) & 3) * 16 + edl;
                rh_s[en0 * 68 + d]        = rv[rr - 1][0] * h_s[en0 * 68 + d];
                rh_s[(en0 + 32) * 68 + d] = rv[rr - 1][1] * h_s[(en0 + 32) * 68 + d];
            }
        }
        __syncthreads();

        {   // cand V-phase (d-split)
            u64t acc[5][2];
            #pragma unroll
            for (int k = 0; k < 5; ++k) { acc[k][0] = acc[k][1] = 0; }
            const float* h0p = rh_s + rg * 68 + dh * 32;
            const float* h1p = rh_s + (rg + 32) * 68 + dh * 32;
            const float* wbase = wc_h + jg * 2 + dh * 512;
            #pragma unroll 2
            for (int d4 = 0; d4 < 32; d4 += 4) {
                float4 hv0 = *(const float4*)(h0p + d4);
                float4 hv1 = *(const float4*)(h1p + d4);
                float h0a[4] = {hv0.x, hv0.y, hv0.z, hv0.w};
                float h1a[4] = {hv1.x, hv1.y, hv1.z, hv1.w};
                #pragma unroll
                for (int q = 0; q < 4; ++q) {
                    u64t a0 = pack_dup(h0a[q]);
                    u64t a1 = pack_dup(h1a[q]);
                    #pragma unroll
                    for (int k = 0; k < 5; ++k) {
                        u64t w = *(const u64t*)(wbase + k * 1024 + (d4 + q) * 16);
                        fma2(acc[k][0], a0, w);
                        fma2(acc[k][1], a1, w);
                    }
                }
            }
            if (dh == 0) {
                #pragma unroll
                for (int k = 0; k < 5; ++k) {
                    *(u64t*)(V_s + k * 2304 + rg * 36 + jg * 2)        = acc[k][0];
                    *(u64t*)(V_s + k * 2304 + (rg + 32) * 36 + jg * 2) = acc[k][1];
                }
            }
            __syncthreads();
            if (dh == 1) {
                #pragma unroll
                for (int k = 0; k < 5; ++k) {
                    float* p0 = V_s + k * 2304 + rg * 36 + jg * 2;
                    float* p1 = V_s + k * 2304 + (rg + 32) * 36 + jg * 2;
                    u64t c0v = *(u64t*)p0;
                    u64t c1v = *(u64t*)p1;
                    fma2(c0v, ONE, acc[k][0]);
                    fma2(c1v, ONE, acc[k][1]);
                    *(u64t*)p0 = c0v;
                    *(u64t*)p1 = c1v;
                }
            }
            __syncthreads();
        }

        {   // cand M-apply (k-split) + GRU update
            u64t y0, y1;
            if (dh == 0) {
                float2 v0 = *(const float2*)(V_s + mg * 36 + ja2);
                float2 v1 = *(const float2*)(V_s + (mg + 32) * 36 + ja2);
                y0 = pack2(cA.x + v0.x, cA.y + v0.y);
                y1 = pack2(cB.x + v1.x, cB.y + v1.y);
            } else {
                y0 = y1 = pack_dup(0.f);
            }
            const int kb = 1 + dh * 2;
            #pragma unroll
            for (int kk = 0; kk < 2; ++kk) {
                const float* Mk = Ms + (kb - 1 + kk) * 4352;
                const float* Vk = V_s + (kb + kk) * 2304;
                #pragma unroll 4
                for (int m = 0; m < 64; m += 4) {
                    float4 mA = *(const float4*)(Mk + mg * 68 + m);
                    float4 mB = *(const float4*)(Mk + (mg + 32) * 68 + m);
                    float mAa[4] = {mA.x, mA.y, mA.z, mA.w};
                    float mBa[4] = {mB.x, mB.y, mB.z, mB.w};
                    #pragma unroll
                    for (int q = 0; q < 4; ++q) {
                        u64t v = *(const u64t*)(Vk + (m + q) * 36 + ja2);
                        fma2(y0, pack_dup(mAa[q]), v);
                        fma2(y1, pack_dup(mBa[q]), v);
                    }
                }
            }
            if (dh == 1) {
                *(u64t*)(yP + s5 * 4)     = y0;
                *(u64t*)(yP + s5 * 4 + 2) = y1;
            }
            __syncthreads();
            if (dh == 0) {
                u64t pa = *(const u64t*)(yP + s5 * 4);
                u64t pb = *(const u64t*)(yP + s5 * 4 + 2);
                fma2(y0, ONE, pa);
                fma2(y1, ONE, pb);
                float* hout0 = d_out0 + ((size_t)(b * T_ + t)) * 4096;
                float2 cc0 = unpack2(y0), cc1 = unpack2(y1);
                float cand0[2] = {cc0.x, cc0.y};
                float cand1[2] = {cc1.x, cc1.y};
                #pragma unroll
                for (int q = 0; q < 2; ++q) {
                    int cl = ja2 + q;
                    int col = j * 16 + cl;
                    float cv0 = tanh_f(cand0[q]);
                    float ug0 = ugs[mg * 17 + cl];
                    float hn0 = ug0 * h_s[mg * 68 + col] + (1.f - ug0) * cv0;
                    hst[mg * 17 + cl] = hn0;
                    float cv1 = tanh_f(cand1[q]);
                    float ug1 = ugs[(mg + 32) * 17 + cl];
                    float hn1 = ug1 * h_s[(mg + 32) * 68 + col] + (1.f - ug1) * cv1;
                    hst[(mg + 32) * 17 + cl] = hn1;
                    if (layer == 0) {
                        hout0[mg * 64 + col]        = hn0;
                        hout0[(mg + 32) * 64 + col] = hn1;
                    } else if (t == idx_t) {
                        d_last[(size_t)b * 4096 + mg * 64 + col]        = hn0;
                        d_last[(size_t)b * 4096 + (mg + 32) * 64 + col] = hn1;
                    }
                }
            }
            __syncthreads();
        }

        // h exchange
        CLUSTER_ARRIVE();
        {
            h_s[en0 * 68 + j * 16 + edl]        = hst[en0 * 17 + edl];
            h_s[(en0 + 32) * 68 + j * 16 + edl] = hst[(en0 + 32) * 17 + edl];
        }
        CLUSTER_WAIT();
        {
            float hv[3][2];
            #pragma unroll
            for (int rr = 1; rr < 4; ++rr) {
                uint32_t hb = hbase[(j + rr) & 3];
                hv[rr - 1][0] = ldc_f32(hb + eoff0);
                hv[rr - 1][1] = ldc_f32(hb + eoff1);
            }
            #pragma unroll
            for (int rr = 1; rr < 4; ++rr) {
                int d = ((j + rr) & 3) * 16 + edl;
                h_s[en0 * 68 + d]        = hv[rr - 1][0];
                h_s[(en0 + 32) * 68 + d] = hv[rr - 1][1];
            }
        }
    }
    CLUSTER_SYNC();
}

// ---------------------------------------------------------------------------
__global__ void final_kernel(const float* __restrict__ Wp, const float* __restrict__ bp,
                             float* __restrict__ out)
{
    __shared__ float red[64 * 4];
    const int b = blockIdx.x, n = threadIdx.x;
    const float* h = d_last + (size_t)b * 4096 + n * 64;
    float l0 = bp[0], l1 = bp[1], l2 = bp[2], l3 = bp[3];
    #pragma unroll 8
    for (int d = 0; d < 64; ++d) {
        float v = fmaxf(h[d], 0.f);
        l0 += v * Wp[d * 4 + 0];
        l1 += v * Wp[d * 4 + 1];
        l2 += v * Wp[d * 4 + 2];
        l3 += v * Wp[d * 4 + 3];
    }
    red[n * 4 + 0] = l0; red[n * 4 + 1] = l1; red[n * 4 + 2] = l2; red[n * 4 + 3] = l3;
    __syncthreads();
    for (int s = 32; s > 0; s >>= 1) {
        if (n < s) {
            #pragma unroll
            for (int c = 0; c < 4; ++c)
                red[n * 4 + c] = fmaxf(red[n * 4 + c], red[(n + s) * 4 + c]);
        }
        __syncthreads();
    }
    if (n < 4) out[b * 4 + n] = red[n];
}

// ---------------------------------------------------------------------------
extern "C" void kernel_launch(void* const* d_in, const int* in_sizes, int n_in,
                              void* d_out, int out_size)
{
    (void)in_sizes; (void)n_in; (void)out_size;
    const float* X   = (const float*)d_in[0];
    const int*   len = (const int*)  d_in[1];
    const float* S0  = (const float*)d_in[2];
    const float* S1  = (const float*)d_in[3];
    const float* Wg0 = (const float*)d_in[4];
    const float* bg0 = (const float*)d_in[5];
    const float* Wc0 = (const float*)d_in[6];
    const float* bc0 = (const float*)d_in[7];
    const float* Wg1 = (const float*)d_in[8];
    const float* bg1 = (const float*)d_in[9];
    const float* Wc1 = (const float*)d_in[10];
    const float* bc1 = (const float*)d_in[11];
    const float* Wp  = (const float*)d_in[12];
    const float* bp  = (const float*)d_in[13];
    float* out = (float*)d_out;

    cudaFuncSetAttribute(pre_wmma,    cudaFuncAttributeMaxDynamicSharedMemorySize, PRE2_SMEM);
    cudaFuncSetAttribute(scan_kernel, cudaFuncAttributeMaxDynamicSharedMemorySize, SCAN_SMEM_BYTES);

    prep_kernel<<<2, 256>>>(S0, S1);
    prep_img<<<64, 256>>>(Wg0, Wc0, Wg1, Wc1);
    pre_wmma<<<B_ * T_, 256, PRE2_SMEM>>>(X, bg0, bc0, 0);
    scan_kernel<<<128, 512, SCAN_SMEM_BYTES>>>(Wg0, Wc0, len, 0);
    pre_wmma<<<B_ * T_, 256, PRE2_SMEM>>>(X, bg1, bc1, 1);
    scan_kernel<<<128, 512, SCAN_SMEM_BYTES>>>(Wg1, Wc1, len, 1);
    final_kernel<<<B_, 64>>>(Wp, bp, out);
}

// round 15
// speedup vs baseline: 1.5151x; 1.1014x over previous
#include <cuda_runtime.h>
#include <cuda_bf16.h>
#include <mma.h>
#include <math.h>
#include <stdint.h>

using namespace nvcuda;

#define B_ 32
#define T_ 128

typedef unsigned long long u64t;

// ---------------- device globals ----------------
__device__ float d_M[4 * 4096];
__device__ float d_out0[B_ * T_ * 4096];
__device__ float d_last[B_ * 4096];
__device__ float d_Gx[(size_t)B_ * T_ * 64 * 128];
__device__ float d_Cx[(size_t)B_ * T_ * 64 * 64];
__device__ __align__(16) unsigned char d_MI[2 * 32768];      // [prec][256x64 bf16]
__device__ __align__(16) unsigned char d_WI[2 * 2 * 122880]; // [layer][prec][320x192 bf16]

// ---------------- helpers ----------------
__device__ __forceinline__ u64t pack_dup(float x) {
    u64t r; asm("mov.b64 %0, {%1,%1};" : "=l"(r) : "f"(x)); return r;
}
__device__ __forceinline__ u64t pack2(float lo, float hi) {
    u64t r; asm("mov.b64 %0, {%1,%2};" : "=l"(r) : "f"(lo), "f"(hi)); return r;
}
__device__ __forceinline__ float2 unpack2(u64t v) {
    float2 f; asm("mov.b64 {%0,%1}, %2;" : "=f"(f.x), "=f"(f.y) : "l"(v)); return f;
}
__device__ __forceinline__ void fma2(u64t& d, u64t a, u64t b) {
    asm("fma.rn.f32x2 %0, %1, %2, %0;" : "+l"(d) : "l"(a), "l"(b));
}
__device__ __forceinline__ uint32_t s_u32(const void* p) {
    return (uint32_t)__cvta_generic_to_shared(p);
}
__device__ __forceinline__ uint32_t mapa_rank(uint32_t a, uint32_t r) {
    uint32_t o;
    asm("mapa.shared::cluster.u32 %0, %1, %2;" : "=r"(o) : "r"(a), "r"(r));
    return o;
}
__device__ __forceinline__ float ldc_f32(uint32_t a) {
    float v;
    asm volatile("ld.shared::cluster.f32 %0, [%1];" : "=f"(v) : "r"(a));
    return v;
}
__device__ __forceinline__ void cp16(void* dst, const void* src) {
    asm volatile("cp.async.cg.shared.global [%0], [%1], 16;"
                 :: "r"(s_u32(dst)), "l"(src));
}
#define CP_COMMIT() asm volatile("cp.async.commit_group;")
#define CP_WAIT0()  asm volatile("cp.async.wait_group 0;")
#define CP_WAIT1()  asm volatile("cp.async.wait_group 1;")
#define CLUSTER_ARRIVE() asm volatile("barrier.cluster.arrive.aligned;" ::: "memory")
#define CLUSTER_WAIT()   asm volatile("barrier.cluster.wait.aligned;"   ::: "memory")
#define CLUSTER_SYNC() do { CLUSTER_ARRIVE(); CLUSTER_WAIT(); } while (0)

__device__ __forceinline__ float sigmoid_f(float v) {
    return __fdividef(1.f, 1.f + __expf(-v));
}
__device__ __forceinline__ float tanh_f(float v) {
    return 1.f - __fdividef(2.f, __expf(2.f * v) + 1.f);
}

extern __shared__ float smem[];

// ---------------------------------------------------------------------------
__global__ void prep_kernel(const float* __restrict__ S0, const float* __restrict__ S1)
{
    __shared__ float Ss[64 * 64];
    const int s = blockIdx.x;
    const float* S = s ? S1 : S0;
    for (int i = threadIdx.x; i < 4096; i += blockDim.x) Ss[i] = S[i];
    __syncthreads();
    for (int i = threadIdx.x; i < 4096; i += blockDim.x) {
        int m = i >> 6, n = i & 63;
        float acc = 0.f;
        #pragma unroll 8
        for (int p = 0; p < 64; ++p) acc += Ss[m * 64 + p] * Ss[p * 64 + n];
        d_M[(2 * s) * 4096 + i]     = Ss[i];
        d_M[(2 * s + 1) * 4096 + i] = 2.f * acc - (m == n ? 1.f : 0.f);
    }
}

// ---------------------------------------------------------------------------
__global__ void prep_img(const float* __restrict__ Wg0, const float* __restrict__ Wc0,
                         const float* __restrict__ Wg1, const float* __restrict__ Wc1)
{
    const int gt = blockIdx.x * blockDim.x + threadIdx.x;
    const int gs = gridDim.x * blockDim.x;
    for (int i = gt; i < 16384; i += gs) {
        int np = i >> 6, n = i & 63;
        float v = d_M[(np >> 6) * 4096 + (np & 63) * 64 + n];
        __nv_bfloat16 hi = __float2bfloat16(v);
        __nv_bfloat16 lo = __float2bfloat16(v - __bfloat162float(hi));
        *(__nv_bfloat16*)(d_MI + np * 128 + n * 2) = hi;
        *(__nv_bfloat16*)(d_MI + 32768 + np * 128 + n * 2) = lo;
    }
    for (int i = gt; i < 2 * 61440; i += gs) {
        int l = i / 61440, rem = i % 61440;
        int kcat = rem / 192, c = rem % 192;
        int kt = kcat >> 6, kk = kcat & 63;
        float v;
        if (c < 128) v = (l ? Wg1 : Wg0)[(size_t)(kt * 128 + kk) * 128 + c];
        else         v = (l ? Wc1 : Wc0)[(size_t)(kt * 128 + kk) * 64 + (c - 128)];
        __nv_bfloat16 hi = __float2bfloat16(v);
        __nv_bfloat16 lo = __float2bfloat16(v - __bfloat162float(hi));
        unsigned char* base = d_WI + l * 245760;
        *(__nv_bfloat16*)(base + kcat * 384 + c * 2) = hi;
        *(__nv_bfloat16*)(base + 122880 + kcat * 384 + c * 2) = lo;
    }
}

// ---------------------------------------------------------------------------
// WMMA precompute of Gx/Cx (R14, unchanged).
// ---------------------------------------------------------------------------
#define PRE2_SMEM (83968 + 102400)

__global__ void __launch_bounds__(256, 1)
pre_wmma(const float* __restrict__ Xin, const float* __restrict__ bg,
         const float* __restrict__ bc, int layer)
{
    unsigned char* sm  = (unsigned char*)smem;
    __nv_bfloat16* A2h = (__nv_bfloat16*)sm;
    __nv_bfloat16* A2l = (__nv_bfloat16*)(sm + 41984);
    unsigned char* SCR = sm + 83968;

    const int tid = threadIdx.x;
    const int w = tid >> 5;
    const int bt = blockIdx.x;

    for (int i = tid; i < 4096; i += 256) {
        int prec = i >> 11, r2 = i & 2047, row = r2 >> 3, c = r2 & 7;
        cp16(SCR + prec * 36864 + row * 144 + c * 16,
             d_MI + prec * 32768 + row * 128 + c * 16);
    }
    CP_COMMIT();
    const float* xsrc = (layer ? d_out0 : Xin) + (size_t)bt * 4096;
    for (int i = tid; i < 4096; i += 256) {
        int n = i >> 6, f = i & 63;
        float v = xsrc[i];
        __nv_bfloat16 hi = __float2bfloat16(v);
        __nv_bfloat16 lo = __float2bfloat16(v - __bfloat162float(hi));
        A2h[n * 328 + f] = hi;
        A2l[n * 328 + f] = lo;
    }
    CP_WAIT0();
    __syncthreads();

    {
        wmma::fragment<wmma::accumulator, 16, 16, 16, float> acc1[8];
        #pragma unroll
        for (int i = 0; i < 8; ++i) wmma::fill_fragment(acc1[i], 0.f);
        const __nv_bfloat16* Mh = (const __nv_bfloat16*)SCR;
        const __nv_bfloat16* Ml = (const __nv_bfloat16*)(SCR + 36864);
        #pragma unroll
        for (int ks = 0; ks < 4; ++ks) {
            wmma::fragment<wmma::matrix_a, 16, 16, 16, __nv_bfloat16, wmma::row_major> ah[2], al[2];
            wmma::fragment<wmma::matrix_b, 16, 16, 16, __nv_bfloat16, wmma::row_major> bh[4], bl[4];
            #pragma unroll
            for (int mi = 0; mi < 2; ++mi) {
                wmma::load_matrix_sync(ah[mi], Mh + (w * 2 + mi) * 16 * 72 + ks * 16, 72);
                wmma::load_matrix_sync(al[mi], Ml + (w * 2 + mi) * 16 * 72 + ks * 16, 72);
            }
            #pragma unroll
            for (int nt = 0; nt < 4; ++nt) {
                wmma::load_matrix_sync(bh[nt], A2h + ks * 16 * 328 + nt * 16, 328);
                wmma::load_matrix_sync(bl[nt], A2l + ks * 16 * 328 + nt * 16, 328);
            }
            #pragma unroll
            for (int mi = 0; mi < 2; ++mi)
                #pragma unroll
                for (int nt = 0; nt < 4; ++nt) {
                    int x = mi * 4 + nt;
                    wmma::mma_sync(acc1[x], ah[mi], bh[nt], acc1[x]);
                    wmma::mma_sync(acc1[x], al[mi], bh[nt], acc1[x]);
                    wmma::mma_sync(acc1[x], ah[mi], bl[nt], acc1[x]);
                }
        }
        __syncthreads();
        float* S = (float*)SCR;
        #pragma unroll
        for (int mi = 0; mi < 2; ++mi)
            #pragma unroll
            for (int nt = 0; nt < 4; ++nt)
                wmma::store_matrix_sync(S + (w * 2 + mi) * 16 * 72 + nt * 16,
                                        acc1[mi * 4 + nt], 72, wmma::mem_row_major);
        __syncthreads();
        for (int i = tid; i < 16384; i += 256) {
            int row = i >> 6, f = i & 63;
            int k = row >> 6, m = row & 63;
            float v = S[row * 72 + f];
            __nv_bfloat16 hi = __float2bfloat16(v);
            __nv_bfloat16 lo = __float2bfloat16(v - __bfloat162float(hi));
            A2h[m * 328 + (k + 1) * 64 + f] = hi;
            A2l[m * 328 + (k + 1) * 64 + f] = lo;
        }
        __syncthreads();
    }

    {
        wmma::fragment<wmma::accumulator, 16, 16, 16, float> acc2[6];
        #pragma unroll
        for (int i = 0; i < 6; ++i) wmma::fill_fragment(acc2[i], 0.f);
        const int mt = w >> 1, ng = w & 1;
        const unsigned char* gW = d_WI + layer * 245760;

        {
            unsigned char* dst = SCR;
            for (int i = tid; i < 1536; i += 256) {
                int row = i / 24, c = i % 24;
                cp16(dst + row * 400 + c * 16, gW + row * 384 + c * 16);
                cp16(dst + 25600 + row * 400 + c * 16, gW + 122880 + row * 384 + c * 16);
            }
            CP_COMMIT();
        }

        for (int kt = 0; kt < 5; ++kt) {
            if (kt < 4) {
                unsigned char* dst = SCR + ((kt + 1) & 1) * 51200;
                const unsigned char* srcH = gW + (kt + 1) * 24576;
                const unsigned char* srcL = gW + 122880 + (kt + 1) * 24576;
                for (int i = tid; i < 1536; i += 256) {
                    int row = i / 24, c = i % 24;
                    cp16(dst + row * 400 + c * 16, srcH + row * 384 + c * 16);
                    cp16(dst + 25600 + row * 400 + c * 16, srcL + row * 384 + c * 16);
                }
            }
            CP_COMMIT();
            CP_WAIT1();
            __syncthreads();

            const __nv_bfloat16* WbH = (const __nv_bfloat16*)(SCR + (kt & 1) * 51200);
            const __nv_bfloat16* WbL = (const __nv_bfloat16*)(SCR + (kt & 1) * 51200 + 25600);
            #pragma unroll
            for (int ks = 0; ks < 4; ++ks) {
                wmma::fragment<wmma::matrix_a, 16, 16, 16, __nv_bfloat16, wmma::row_major> ah, al;
                wmma::load_matrix_sync(ah, A2h + mt * 16 * 328 + kt * 64 + ks * 16, 328);
                wmma::load_matrix_sync(al, A2l + mt * 16 * 328 + kt * 64 + ks * 16, 328);
                #pragma unroll
                for (int nt = 0; nt < 6; ++nt) {
                    wmma::fragment<wmma::matrix_b, 16, 16, 16, __nv_bfloat16, wmma::row_major> bh, bl;
                    int nc = (ng * 6 + nt) * 16;
                    wmma::load_matrix_sync(bh, WbH + ks * 16 * 200 + nc, 200);
                    wmma::load_matrix_sync(bl, WbL + ks * 16 * 200 + nc, 200);
                    wmma::mma_sync(acc2[nt], ah, bh, acc2[nt]);
                    wmma::mma_sync(acc2[nt], al, bh, acc2[nt]);
                    wmma::mma_sync(acc2[nt], ah, bl, acc2[nt]);
                }
            }
            __syncthreads();
        }

        float* S = (float*)SCR;
        #pragma unroll
        for (int nt = 0; nt < 6; ++nt)
            wmma::store_matrix_sync(S + mt * 16 * 200 + (ng * 6 + nt) * 16,
                                    acc2[nt], 200, wmma::mem_row_major);
        __syncthreads();
        for (int i = tid; i < 12288; i += 256) {
            int n = i / 192, c = i % 192;
            float v = S[n * 200 + c];
            if (c < 128) d_Gx[(size_t)bt * 8192 + n * 128 + c] = v + bg[c];
            else         d_Cx[(size_t)bt * 4096 + n * 64 + (c - 128)] = v + bc[c - 128];
        }
    }
}

// ---------------------------------------------------------------------------
// Scan v7: V-phases on wmma (W pre-split bf16 in SMEM, h as exact hi/lo bf16);
// M-applies fp32 fma2 k-split; exchange protocol unchanged.
// smem (bytes): WIh 0(33792) WIl 33792(33792) Ms 67584(69632)
//   Vs 137216(41984 fp32 64x164) hH 179200(9216 64x72) hL 188416(9216)
//   h_loc 197632(4352) rst 201984 ugs 206336 hst 210688 (each 4352)
//   yP 215040(8192)  total 223232
// ---------------------------------------------------------------------------
#define SCAN_SMEM_BYTES 223232

__global__ void __launch_bounds__(512, 1) __cluster_dims__(4, 1, 1)
scan_kernel(const float* __restrict__ Wg, const float* __restrict__ Wc,
            const int* __restrict__ lens, int layer)
{
    unsigned char* sm = (unsigned char*)smem;
    __nv_bfloat16* WIh = (__nv_bfloat16*)sm;            // [64 d][264] gate 0..159, cand 160..239
    __nv_bfloat16* WIl = (__nv_bfloat16*)(sm + 33792);
    float* Ms    = (float*)(sm + 67584);                // 4 x [64][68]
    float* Vs    = (float*)(sm + 137216);               // [64][164]
    __nv_bfloat16* hH = (__nv_bfloat16*)(sm + 179200);  // [64][72]
    __nv_bfloat16* hL = (__nv_bfloat16*)(sm + 188416);
    float* h_loc = (float*)(sm + 197632);               // [64][17] local 16 cols
    float* rst   = (float*)(sm + 201984);
    float* ugs   = (float*)(sm + 206336);
    float* hst   = (float*)(sm + 210688);
    float* yP    = (float*)(sm + 215040);

    const int tid = threadIdx.x;
    const int w   = tid >> 5;
    const int b = blockIdx.x >> 2;
    const int j = blockIdx.x & 3;

    // one-time: W images (bf16 split), M fp32, zero h
    for (int i = tid; i < 64 * 240; i += 512) {
        int d = i / 240, o = i % 240;
        float v;
        if (o < 160) {
            int k = o >> 5, c = o & 31;
            int g = (c < 16) ? (j * 16 + c) : (64 + j * 16 + (c - 16));
            v = Wg[(size_t)(k * 128 + 64 + d) * 128 + g];
        } else {
            int oc = o - 160, k = oc >> 4, c = oc & 15;
            v = Wc[(size_t)(k * 128 + 64 + d) * 64 + j * 16 + c];
        }
        __nv_bfloat16 hi = __float2bfloat16(v);
        __nv_bfloat16 lo = __float2bfloat16(v - __bfloat162float(hi));
        WIh[d * 264 + o] = hi;
        WIl[d * 264 + o] = lo;
    }
    for (int i = tid; i < 16384; i += 512) {
        int k = i >> 12, r = (i >> 6) & 63, p = i & 63;
        Ms[k * 4352 + r * 68 + p] = d_M[i];
    }
    for (int i = tid; i < 4096; i += 512) {
        int n = i >> 6, d = i & 63;
        hH[n * 72 + d] = __float2bfloat16(0.f);
        hL[n * 72 + d] = __float2bfloat16(0.f);
        if (d < 17) h_loc[n * 17 + d] = 0.f;
    }

    int idx_t = lens[b] - 1;
    idx_t = idx_t < 0 ? 0 : (idx_t > T_ - 1 ? T_ - 1 : idx_t);

    uint32_t rbase[4], hbase[4];
    #pragma unroll
    for (int r = 0; r < 4; ++r) {
        rbase[r] = mapa_rank(s_u32(rst), (uint32_t)r);
        hbase[r] = mapa_rank(s_u32(hst), (uint32_t)r);
    }

    const int dh  = tid >> 8;
    const int s5  = tid & 255;
    const int mg  = s5 >> 3;
    const int ja4 = (s5 & 7) * 4;
    const int ja2 = (s5 & 7) * 2;
    const int g0  = (ja4 < 16) ? (j * 16 + ja4) : (64 + j * 16 + (ja4 - 16));
    const int c0  = j * 16 + ja2;
    const u64t ONE = pack_dup(1.f);
    const int en0 = tid >> 4, edl = tid & 15;
    const uint32_t eoff0 = (uint32_t)(en0 * 17 + edl) * 4;
    const uint32_t eoff1 = (uint32_t)((en0 + 32) * 17 + edl) * 4;
    const int rt = w & 3;   // wmma row-tile for this warp

    const float* gxb = d_Gx + (size_t)b * T_ * 8192;
    const float* cxb = d_Cx + (size_t)b * T_ * 4096;

    for (int t = 0; t < T_; ++t) {
        __syncthreads();

        float4 gA = make_float4(0.f, 0.f, 0.f, 0.f);
        float4 gB = gA;
        float2 cA = make_float2(0.f, 0.f);
        float2 cB = cA;
        if (dh == 0) {
            const float* gx = gxb + (size_t)t * 8192;
            const float* cx = cxb + (size_t)t * 4096;
            gA = __ldg((const float4*)(gx + mg * 128 + g0));
            gB = __ldg((const float4*)(gx + (mg + 32) * 128 + g0));
            cA = __ldg((const float2*)(cx + mg * 64 + c0));
            cB = __ldg((const float2*)(cx + (mg + 32) * 64 + c0));
        }

        // ---------- gate V-phase: wmma, V[64][160] = h(64x64) @ WI[:,0:160] ----------
        {
            wmma::fragment<wmma::matrix_a, 16, 16, 16, __nv_bfloat16, wmma::row_major> a_h[4], a_l[4];
            #pragma unroll
            for (int kf = 0; kf < 4; ++kf) {
                wmma::load_matrix_sync(a_h[kf], hH + rt * 16 * 72 + kf * 16, 72);
                wmma::load_matrix_sync(a_l[kf], hL + rt * 16 * 72 + kf * 16, 72);
            }
            for (int tile = w; tile < 40; tile += 16) {
                int ct = tile >> 2;
                wmma::fragment<wmma::accumulator, 16, 16, 16, float> acc;
                wmma::fill_fragment(acc, 0.f);
                #pragma unroll
                for (int kf = 0; kf < 4; ++kf) {
                    wmma::fragment<wmma::matrix_b, 16, 16, 16, __nv_bfloat16, wmma::row_major> bh, bl;
                    wmma::load_matrix_sync(bh, WIh + kf * 16 * 264 + ct * 16, 264);
                    wmma::load_matrix_sync(bl, WIl + kf * 16 * 264 + ct * 16, 264);
                    wmma::mma_sync(acc, a_h[kf], bh, acc);
                    wmma::mma_sync(acc, a_l[kf], bh, acc);
                    wmma::mma_sync(acc, a_h[kf], bl, acc);
                }
                wmma::store_matrix_sync(Vs + rt * 16 * 164 + ct * 16, acc, 164, wmma::mem_row_major);
            }
        }
        __syncthreads();

        // ---------- gate M-apply (k-split) + sigmoid + stage ----------
        {
            u64t y00, y01, y10, y11;
            if (dh == 0) {
                float4 vA = *(const float4*)(Vs + mg * 164 + ja4);
                float4 vB = *(const float4*)(Vs + (mg + 32) * 164 + ja4);
                y00 = pack2(gA.x + vA.x, gA.y + vA.y);
                y01 = pack2(gA.z + vA.z, gA.w + vA.w);
                y10 = pack2(gB.x + vB.x, gB.y + vB.y);
                y11 = pack2(gB.z + vB.z, gB.w + vB.w);
            } else {
                y00 = y01 = y10 = y11 = pack_dup(0.f);
            }
            const int kb = 1 + dh * 2;
            #pragma unroll
            for (int kk = 0; kk < 2; ++kk) {
                const float* Mk = Ms + (kb - 1 + kk) * 4352;
                const float* Vk = Vs + (kb + kk) * 32;
                #pragma unroll 4
                for (int m = 0; m < 64; m += 4) {
                    float4 mA = *(const float4*)(Mk + mg * 68 + m);
                    float4 mB = *(const float4*)(Mk + (mg + 32) * 68 + m);
                    float mAa[4] = {mA.x, mA.y, mA.z, mA.w};
                    float mBa[4] = {mB.x, mB.y, mB.z, mB.w};
                    #pragma unroll
                    for (int q = 0; q < 4; ++q) {
                        ulonglong2 v = *(const ulonglong2*)(Vk + (m + q) * 164 + ja4);
                        u64t da = pack_dup(mAa[q]);
                        u64t db = pack_dup(mBa[q]);
                        fma2(y00, da, v.x); fma2(y01, da, v.y);
                        fma2(y10, db, v.x); fma2(y11, db, v.y);
                    }
                }
            }
            if (dh == 1) {
                ulonglong2 sv;
                sv.x = y00; sv.y = y01; *(ulonglong2*)(yP + s5 * 8)     = sv;
                sv.x = y10; sv.y = y11; *(ulonglong2*)(yP + s5 * 8 + 4) = sv;
            }
            __syncthreads();
            if (dh == 0) {
                ulonglong2 pa = *(const ulonglong2*)(yP + s5 * 8);
                ulonglong2 pb = *(const ulonglong2*)(yP + s5 * 8 + 4);
                fma2(y00, ONE, pa.x); fma2(y01, ONE, pa.y);
                fma2(y10, ONE, pb.x); fma2(y11, ONE, pb.y);
                float2 p00 = unpack2(y00), p01 = unpack2(y01);
                float2 p10 = unpack2(y10), p11 = unpack2(y11);
                float v0a[4] = {p00.x, p00.y, p01.x, p01.y};
                float v1a[4] = {p10.x, p10.y, p11.x, p11.y};
                #pragma unroll
                for (int q = 0; q < 4; ++q) {
                    int c = ja4 + q;
                    float s0 = sigmoid_f(v0a[q]);
                    float s1 = sigmoid_f(v1a[q]);
                    if (c < 16) { rst[mg * 17 + c] = s0;        rst[(mg + 32) * 17 + c] = s1; }
                    else        { ugs[mg * 17 + c - 16] = s0;   ugs[(mg + 32) * 17 + c - 16] = s1; }
                }
            }
        }

        // r exchange; rh = r*(hH+hL) written back into hH/hL as split
        CLUSTER_ARRIVE();
        __syncthreads();
        {
            int d = j * 16 + edl;
            #pragma unroll
            for (int half = 0; half < 2; ++half) {
                int n = en0 + half * 32;
                float hv = __bfloat162float(hH[n * 72 + d]) + __bfloat162float(hL[n * 72 + d]);
                float rh = rst[n * 17 + edl] * hv;
                __nv_bfloat16 hi = __float2bfloat16(rh);
                hH[n * 72 + d] = hi;
                hL[n * 72 + d] = __float2bfloat16(rh - __bfloat162float(hi));
            }
        }
        CLUSTER_WAIT();
        {
            float rv[3][2];
            #pragma unroll
            for (int rr = 1; rr < 4; ++rr) {
                uint32_t rb = rbase[(j + rr) & 3];
                rv[rr - 1][0] = ldc_f32(rb + eoff0);
                rv[rr - 1][1] = ldc_f32(rb + eoff1);
            }
            #pragma unroll
            for (int rr = 1; rr < 4; ++rr) {
                int d = ((j + rr) & 3) * 16 + edl;
                #pragma unroll
                for (int half = 0; half < 2; ++half) {
                    int n = en0 + half * 32;
                    float hv = __bfloat162float(hH[n * 72 + d]) + __bfloat162float(hL[n * 72 + d]);
                    float rh = rv[rr - 1][half] * hv;
                    __nv_bfloat16 hi = __float2bfloat16(rh);
                    hH[n * 72 + d] = hi;
                    hL[n * 72 + d] = __float2bfloat16(rh - __bfloat162float(hi));
                }
            }
        }
        __syncthreads();

        // ---------- cand V-phase: wmma, V[64][80] = rh(64x64) @ WI[:,160:240] ----------
        {
            wmma::fragment<wmma::matrix_a, 16, 16, 16, __nv_bfloat16, wmma::row_major> a_h[4], a_l[4];
            #pragma unroll
            for (int kf = 0; kf < 4; ++kf) {
                wmma::load_matrix_sync(a_h[kf], hH + rt * 16 * 72 + kf * 16, 72);
                wmma::load_matrix_sync(a_l[kf], hL + rt * 16 * 72 + kf * 16, 72);
            }
            for (int tile = w; tile < 20; tile += 16) {
                int ct = tile >> 2;
                wmma::fragment<wmma::accumulator, 16, 16, 16, float> acc;
                wmma::fill_fragment(acc, 0.f);
                #pragma unroll
                for (int kf = 0; kf < 4; ++kf) {
                    wmma::fragment<wmma::matrix_b, 16, 16, 16, __nv_bfloat16, wmma::row_major> bh, bl;
                    wmma::load_matrix_sync(bh, WIh + kf * 16 * 264 + 160 + ct * 16, 264);
                    wmma::load_matrix_sync(bl, WIl + kf * 16 * 264 + 160 + ct * 16, 264);
                    wmma::mma_sync(acc, a_h[kf], bh, acc);
                    wmma::mma_sync(acc, a_l[kf], bh, acc);
                    wmma::mma_sync(acc, a_h[kf], bl, acc);
                }
                wmma::store_matrix_sync(Vs + rt * 16 * 164 + ct * 16, acc, 164, wmma::mem_row_major);
            }
        }
        __syncthreads();

        // ---------- cand M-apply (k-split) + GRU update ----------
        {
            u64t y0, y1;
            if (dh == 0) {
                float2 v0 = *(const float2*)(Vs + mg * 164 + ja2);
                float2 v1 = *(const float2*)(Vs + (mg + 32) * 164 + ja2);
                y0 = pack2(cA.x + v0.x, cA.y + v0.y);
                y1 = pack2(cB.x + v1.x, cB.y + v1.y);
            } else {
                y0 = y1 = pack_dup(0.f);
            }
            const int kb = 1 + dh * 2;
            #pragma unroll
            for (int kk = 0; kk < 2; ++kk) {
                const float* Mk = Ms + (kb - 1 + kk) * 4352;
                const float* Vk = Vs + (kb + kk) * 16;
                #pragma unroll 4
                for (int m = 0; m < 64; m += 4) {
                    float4 mA = *(const float4*)(Mk + mg * 68 + m);
                    float4 mB = *(const float4*)(Mk + (mg + 32) * 68 + m);
                    float mAa[4] = {mA.x, mA.y, mA.z, mA.w};
                    float mBa[4] = {mB.x, mB.y, mB.z, mB.w};
                    #pragma unroll
                    for (int q = 0; q < 4; ++q) {
                        u64t v = *(const u64t*)(Vk + (m + q) * 164 + ja2);
                        fma2(y0, pack_dup(mAa[q]), v);
                        fma2(y1, pack_dup(mBa[q]), v);
                    }
                }
            }
            if (dh == 1) {
                *(u64t*)(yP + s5 * 4)     = y0;
                *(u64t*)(yP + s5 * 4 + 2) = y1;
            }
            __syncthreads();
            if (dh == 0) {
                u64t pa = *(const u64t*)(yP + s5 * 4);
                u64t pb = *(const u64t*)(yP + s5 * 4 + 2);
                fma2(y0, ONE, pa);
                fma2(y1, ONE, pb);
                float* hout0 = d_out0 + ((size_t)(b * T_ + t)) * 4096;
                float2 cc0 = unpack2(y0), cc1 = unpack2(y1);
                float cand0[2] = {cc0.x, cc0.y};
                float cand1[2] = {cc1.x, cc1.y};
                #pragma unroll
                for (int q = 0; q < 2; ++q) {
                    int cl = ja2 + q;
                    int col = j * 16 + cl;
                    float cv0 = tanh_f(cand0[q]);
                    float ug0 = ugs[mg * 17 + cl];
                    float hn0 = ug0 * h_loc[mg * 17 + cl] + (1.f - ug0) * cv0;
                    hst[mg * 17 + cl] = hn0;
                    float cv1 = tanh_f(cand1[q]);
                    float ug1 = ugs[(mg + 32) * 17 + cl];
                    float hn1 = ug1 * h_loc[(mg + 32) * 17 + cl] + (1.f - ug1) * cv1;
                    hst[(mg + 32) * 17 + cl] = hn1;
                    if (layer == 0) {
                        hout0[mg * 64 + col]        = hn0;
                        hout0[(mg + 32) * 64 + col] = hn1;
                    } else if (t == idx_t) {
                        d_last[(size_t)b * 4096 + mg * 64 + col]        = hn0;
                        d_last[(size_t)b * 4096 + (mg + 32) * 64 + col] = hn1;
                    }
                }
            }
        }

        // h exchange: write new h split (+ local fp32 quarter)
        CLUSTER_ARRIVE();
        __syncthreads();
        {
            int d = j * 16 + edl;
            #pragma unroll
            for (int half = 0; half < 2; ++half) {
                int n = en0 + half * 32;
                float hv = hst[n * 17 + edl];
                __nv_bfloat16 hi = __float2bfloat16(hv);
                hH[n * 72 + d] = hi;
                hL[n * 72 + d] = __float2bfloat16(hv - __bfloat162float(hi));
                h_loc[n * 17 + edl] = hv;
            }
        }
        CLUSTER_WAIT();
        {
            float hv[3][2];
            #pragma unroll
            for (int rr = 1; rr < 4; ++rr) {
                uint32_t hb = hbase[(j + rr) & 3];
                hv[rr - 1][0] = ldc_f32(hb + eoff0);
                hv[rr - 1][1] = ldc_f32(hb + eoff1);
            }
            #pragma unroll
            for (int rr = 1; rr < 4; ++rr) {
                int d = ((j + rr) & 3) * 16 + edl;
                #pragma unroll
                for (int half = 0; half < 2; ++half) {
                    int n = en0 + half * 32;
                    float v = hv[rr - 1][half];
                    __nv_bfloat16 hi = __float2bfloat16(v);
                    hH[n * 72 + d] = hi;
                    hL[n * 72 + d] = __float2bfloat16(v - __bfloat162float(hi));
                }
            }
        }
    }
    CLUSTER_SYNC();
}

// ---------------------------------------------------------------------------
__global__ void final_kernel(const float* __restrict__ Wp, const float* __restrict__ bp,
                             float* __restrict__ out)
{
    __shared__ float red[64 * 4];
    const int b = blockIdx.x, n = threadIdx.x;
    const float* h = d_last + (size_t)b * 4096 + n * 64;
    float l0 = bp[0], l1 = bp[1], l2 = bp[2], l3 = bp[3];
    #pragma unroll 8
    for (int d = 0; d < 64; ++d) {
        float v = fmaxf(h[d], 0.f);
        l0 += v * Wp[d * 4 + 0];
        l1 += v * Wp[d * 4 + 1];
        l2 += v * Wp[d * 4 + 2];
        l3 += v * Wp[d * 4 + 3];
    }
    red[n * 4 + 0] = l0; red[n * 4 + 1] = l1; red[n * 4 + 2] = l2; red[n * 4 + 3] = l3;
    __syncthreads();
    for (int s = 32; s > 0; s >>= 1) {
        if (n < s) {
            #pragma unroll
            for (int c = 0; c < 4; ++c)
                red[n * 4 + c] = fmaxf(red[n * 4 + c], red[(n + s) * 4 + c]);
        }
        __syncthreads();
    }
    if (n < 4) out[b * 4 + n] = red[n];
}

// ---------------------------------------------------------------------------
extern "C" void kernel_launch(void* const* d_in, const int* in_sizes, int n_in,
                              void* d_out, int out_size)
{
    (void)in_sizes; (void)n_in; (void)out_size;
    const float* X   = (const float*)d_in[0];
    const int*   len = (const int*)  d_in[1];
    const float* S0  = (const float*)d_in[2];
    const float* S1  = (const float*)d_in[3];
    const float* Wg0 = (const float*)d_in[4];
    const float* bg0 = (const float*)d_in[5];
    const float* Wc0 = (const float*)d_in[6];
    const float* bc0 = (const float*)d_in[7];
    const float* Wg1 = (const float*)d_in[8];
    const float* bg1 = (const float*)d_in[9];
    const float* Wc1 = (const float*)d_in[10];
    const float* bc1 = (const float*)d_in[11];
    const float* Wp  = (const float*)d_in[12];
    const float* bp  = (const float*)d_in[13];
    float* out = (float*)d_out;

    cudaFuncSetAttribute(pre_wmma,    cudaFuncAttributeMaxDynamicSharedMemorySize, PRE2_SMEM);
    cudaFuncSetAttribute(scan_kernel, cudaFuncAttributeMaxDynamicSharedMemorySize, SCAN_SMEM_BYTES);

    prep_kernel<<<2, 256>>>(S0, S1);
    prep_img<<<64, 256>>>(Wg0, Wc0, Wg1, Wc1);
    pre_wmma<<<B_ * T_, 256, PRE2_SMEM>>>(X, bg0, bc0, 0);
    scan_kernel<<<128, 512, SCAN_SMEM_BYTES>>>(Wg0, Wc0, len, 0);
    pre_wmma<<<B_ * T_, 256, PRE2_SMEM>>>(X, bg1, bc1, 1);
    scan_kernel<<<128, 512, SCAN_SMEM_BYTES>>>(Wg1, Wc1, len, 1);
    final_kernel<<<B_, 64>>>(Wp, bp, out);
}